// round 12
// baseline (speedup 1.0000x reference)
#include <cuda_runtime.h>
#include <cuda_bf16.h>
#include <cuda_fp16.h>
#include <cstdint>

#define MAXN 50000
#define MAXE 800000
#define K_DIM 128

// ---------------- scratch (__device__ globals; no allocs allowed) ----------------
__device__ float  g_dinv[MAXN];
__device__ int    g_deg[MAXN];
__device__ int    g_rowptr[MAXN + 1];
__device__ int    g_cursor[MAXN];
__device__ int    g_bsum[256];
__device__ int    g_boff[256];
__device__ int    g_arrive;
__device__ int    g_arrive2;
__device__ int    g_flag;
__device__ float2 g_csr[MAXE];
__device__ uint16_t g_h1[(size_t)MAXN * 128];   // fp16 gather buffer (layer 1)
__device__ float    g_buf1[(size_t)MAXN * 128];
__device__ uint16_t g_h2[(size_t)MAXN * 64];    // fp16 gather buffer (layer 2)
// bf16 split weights, plain row-major [k][n]
__device__ uint16_t g_w1h[128 * 128], g_w1l[128 * 128];
__device__ uint16_t g_w2h[128 * 64],  g_w2l[128 * 64];

// ---------------- packed f32x2 helpers (agg path) ----------------
__device__ __forceinline__ unsigned long long packdup(float x) {
    unsigned long long r;
    asm("mov.b64 %0, {%1, %1};" : "=l"(r) : "f"(x));
    return r;
}
__device__ __forceinline__ unsigned long long pack2(float x, float y) {
    unsigned long long r;
    asm("mov.b64 %0, {%1, %2};" : "=l"(r) : "f"(x), "f"(y));
    return r;
}
__device__ __forceinline__ unsigned long long ffma2v(unsigned long long a,
                                                     unsigned long long b,
                                                     unsigned long long c) {
    unsigned long long d;
    asm("fma.rn.f32x2 %0, %1, %2, %3;" : "=l"(d) : "l"(a), "l"(b), "l"(c));
    return d;
}
__device__ __forceinline__ unsigned long long add2(unsigned long long a,
                                                   unsigned long long b) {
    unsigned long long d;
    asm("add.rn.f32x2 %0, %1, %2;" : "=l"(d) : "l"(a), "l"(b));
    return d;
}
// gather 4 fp16 -> two packed f32x2, fma into acc
__device__ __forceinline__ void fma_h4(unsigned long long& a0, unsigned long long& a1,
                                       uint2 v, unsigned long long nrm) {
    float2 f0 = __half22float2(*(__half2*)&v.x);
    float2 f1 = __half22float2(*(__half2*)&v.y);
    a0 = ffma2v(pack2(f0.x, f0.y), nrm, a0);
    a1 = ffma2v(pack2(f1.x, f1.y), nrm, a1);
}

// ---------------- mma / ldmatrix helpers (sm_80-era, valid at compute_103) ----------------
__device__ __forceinline__ uint32_t smem_u32(const void* p) {
    uint32_t a;
    asm("{ .reg .u64 t; cvta.to.shared.u64 t, %1; cvt.u32.u64 %0, t; }"
        : "=r"(a) : "l"(p));
    return a;
}
__device__ __forceinline__ void mma16816(float* d, const uint32_t* a, const uint32_t* b) {
    asm volatile(
        "mma.sync.aligned.m16n8k16.row.col.f32.bf16.bf16.f32 "
        "{%0,%1,%2,%3}, {%4,%5,%6,%7}, {%8,%9}, {%0,%1,%2,%3};"
        : "+f"(d[0]), "+f"(d[1]), "+f"(d[2]), "+f"(d[3])
        : "r"(a[0]), "r"(a[1]), "r"(a[2]), "r"(a[3]), "r"(b[0]), "r"(b[1]));
}
__device__ __forceinline__ void ldsm_x4(uint32_t* r, uint32_t addr) {
    asm volatile("ldmatrix.sync.aligned.m8n8.x4.shared.b16 {%0,%1,%2,%3}, [%4];"
                 : "=r"(r[0]), "=r"(r[1]), "=r"(r[2]), "=r"(r[3]) : "r"(addr));
}
__device__ __forceinline__ void ldsm_x4t(uint32_t* r, uint32_t addr) {
    asm volatile("ldmatrix.sync.aligned.m8n8.x4.trans.shared.b16 {%0,%1,%2,%3}, [%4];"
                 : "=r"(r[0]), "=r"(r[1]), "=r"(r[2]), "=r"(r[3]) : "r"(addr));
}
__device__ __forceinline__ void split_bf16(float x, uint16_t& hi, uint16_t& lo) {
    __nv_bfloat16 h = __float2bfloat16_rn(x);
    __nv_bfloat16 l = __float2bfloat16_rn(x - __bfloat162float(h));
    hi = __bfloat16_as_ushort(h);
    lo = __bfloat16_as_ushort(l);
}

// ---------------- degree count + weight split (fused; independent work) ----------------
__global__ void k_count_conv(const int* __restrict__ ei, int E,
                             const float* __restrict__ W1,
                             const float* __restrict__ W2) {
    int i = blockIdx.x * blockDim.x + threadIdx.x;
    if (i < E) atomicAdd(&g_deg[ei[E + i]], 1);
    if (i < 128 * 128) {
        uint16_t h, l;
        split_bf16(W1[i], h, l);
        g_w1h[i] = h; g_w1l[i] = l;
    } else if (i < 128 * 128 + 128 * 64) {
        int j = i - 128 * 128;
        uint16_t h, l;
        split_bf16(W2[j], h, l);
        g_w2h[j] = h; g_w2l[j] = l;
    }
}

// Single-pass scan, self-cleaning: zeroes g_deg after reading; last-finishing
// block resets g_arrive/g_flag/g_arrive2 (all spins exited by then).
// Device globals are zero-initialized at load, so call 1 sees clean state.
__global__ void __launch_bounds__(256) k_scan_all(int n, int nb) {
    __shared__ int s[256];
    __shared__ int s_go;
    int t = threadIdx.x, b = blockIdx.x;
    int i = b * 256 + t;
    int v = (i < n) ? g_deg[i] : 0;
    if (i < n) {
        g_dinv[i] = rsqrtf((float)v + 1.0f);
        g_deg[i] = 0;                        // reset for next replay
    }
    s[t] = v;
    __syncthreads();
#pragma unroll
    for (int off = 1; off < 256; off <<= 1) {
        int a = (t >= off) ? s[t - off] : 0;
        __syncthreads();
        s[t] += a;
        __syncthreads();
    }
    int incl = s[t];
    if (t == 255) {
        g_bsum[b] = incl;
        __threadfence();
        int tk = atomicAdd(&g_arrive, 1);
        s_go = (tk == nb - 1);
    }
    __syncthreads();
    if (s_go) {
        int bv2 = (t < nb) ? g_bsum[t] : 0;
        s[t] = bv2;
        __syncthreads();
#pragma unroll
        for (int off = 1; off < 256; off <<= 1) {
            int a = (t >= off) ? s[t - off] : 0;
            __syncthreads();
            s[t] += a;
            __syncthreads();
        }
        if (t < nb) g_boff[t] = s[t] - bv2;
        __threadfence();
        if (t == 0) atomicExch(&g_flag, 1);
    } else {
        if (t == 0) { while (atomicAdd(&g_flag, 0) == 0) { } }
        __syncthreads();
    }
    int boff = *((volatile int*)&g_boff[b]);
    if (i < n) {
        int r = incl - v + boff;
        g_rowptr[i] = r;
        g_cursor[i] = r;
        if (i == n - 1) g_rowptr[n] = r + v;
    }
    __syncthreads();
    if (t == 0) {
        int t2 = atomicAdd(&g_arrive2, 1);
        if (t2 == nb - 1) {                  // everyone exited their spin
            g_flag = 0; g_arrive = 0; g_arrive2 = 0;
            __threadfence();
        }
    }
}

__global__ void k_scatter(const int* __restrict__ ei, int E) {
    int e = blockIdx.x * blockDim.x + threadIdx.x;
    if (e < E) {
        int s = ei[e];
        int d = ei[E + e];
        int pos = atomicAdd(&g_cursor[d], 1);
        g_csr[pos] = make_float2(__int_as_float(s), g_dinv[s] * g_dinv[d]);
    }
}

// ---------------- tensor-core GEMM: Hfp16 = X @ W ; OUT = bias + H*dinv^2 ----------------
template <int NCOL, bool RELU>
__global__ void __launch_bounds__(256, 1) k_gemm_mma(
    const float* __restrict__ X, const float* __restrict__ bias,
    const float* __restrict__ dinv, uint16_t* __restrict__ H16,
    float* __restrict__ OUT, int nrows)
{
    constexpr int PX = 136;
    constexpr int PW = (NCOL == 128) ? 136 : 72;
    constexpr int NT = NCOL / 8;

    extern __shared__ uint16_t sm16[];
    uint16_t* sXh = sm16;
    uint16_t* sXl = sXh + 128 * PX;
    uint16_t* sWh = sXl + 128 * PX;
    uint16_t* sWl = sWh + 128 * PW;

    const int tid  = threadIdx.x;
    const int warp = tid >> 5;
    const int lane = tid & 31;
    const int row0 = blockIdx.x * 128;

    {
        const uint4* gh = (const uint4*)((NCOL == 128) ? g_w1h : g_w2h);
        const uint4* gl = (const uint4*)((NCOL == 128) ? g_w1l : g_w2l);
        for (int i = tid; i < 128 * (NCOL / 8); i += 256) {
            int k = i / (NCOL / 8), c = i % (NCOL / 8);
            ((uint4*)(sWh + k * PW))[c] = gh[i];
            ((uint4*)(sWl + k * PW))[c] = gl[i];
        }
    }

    {
        int r = tid >> 1, half = tid & 1;
        int row = row0 + r;
        uint32_t* dh = (uint32_t*)(sXh + r * PX + half * 64);
        uint32_t* dl = (uint32_t*)(sXl + r * PX + half * 64);
        if (row < nrows) {
            const float4* xr = (const float4*)(X + (size_t)row * K_DIM) + half * 16;
#pragma unroll 4
            for (int c4 = 0; c4 < 16; c4++) {
                float4 v = xr[c4];
                if (RELU) {
                    v.x = fmaxf(v.x, 0.f); v.y = fmaxf(v.y, 0.f);
                    v.z = fmaxf(v.z, 0.f); v.w = fmaxf(v.w, 0.f);
                }
                uint16_t h0, l0, h1, l1, h2, l2, h3, l3;
                split_bf16(v.x, h0, l0); split_bf16(v.y, h1, l1);
                split_bf16(v.z, h2, l2); split_bf16(v.w, h3, l3);
                dh[2 * c4]     = (uint32_t)h0 | ((uint32_t)h1 << 16);
                dh[2 * c4 + 1] = (uint32_t)h2 | ((uint32_t)h3 << 16);
                dl[2 * c4]     = (uint32_t)l0 | ((uint32_t)l1 << 16);
                dl[2 * c4 + 1] = (uint32_t)l2 | ((uint32_t)l3 << 16);
            }
        } else {
#pragma unroll 4
            for (int c4 = 0; c4 < 16; c4++) {
                dh[2 * c4] = 0u; dh[2 * c4 + 1] = 0u;
                dl[2 * c4] = 0u; dl[2 * c4 + 1] = 0u;
            }
        }
    }
    __syncthreads();

    const uint32_t bXh = smem_u32(sXh), bXl = smem_u32(sXl);
    const uint32_t bWh = smem_u32(sWh), bWl = smem_u32(sWl);

    float acc[NT][4];
#pragma unroll
    for (int j = 0; j < NT; j++) {
        acc[j][0] = 0.f; acc[j][1] = 0.f; acc[j][2] = 0.f; acc[j][3] = 0.f;
    }

    const int mrow = warp * 16;
    const uint32_t aoff = ((uint32_t)(mrow + (lane & 15)) * PX + ((lane >> 4) << 3)) * 2;
    const uint32_t boff = ((uint32_t)(lane & 15) * PW + ((lane >> 4) << 3)) * 2;

#pragma unroll
    for (int kt = 0; kt < 8; kt++) {
        uint32_t ah[4], al[4];
        ldsm_x4(ah, bXh + aoff + kt * 32);
        ldsm_x4(al, bXl + aoff + kt * 32);
        uint32_t bk = kt * 16 * PW * 2;
#pragma unroll
        for (int np = 0; np < NT / 2; np++) {
            uint32_t bh[4], bl[4];
            ldsm_x4t(bh, bWh + boff + bk + np * 32);
            ldsm_x4t(bl, bWl + boff + bk + np * 32);
            mma16816(acc[2 * np],     ah, bh);
            mma16816(acc[2 * np + 1], ah, bh + 2);
            mma16816(acc[2 * np],     ah, bl);
            mma16816(acc[2 * np + 1], ah, bl + 2);
            mma16816(acc[2 * np],     al, bh);
            mma16816(acc[2 * np + 1], al, bh + 2);
        }
    }

    {
        int r0g = row0 + mrow + (lane >> 2);
        int r1g = r0g + 8;
        float d20 = 0.f, d21 = 0.f;
        if (r0g < nrows) { float di = dinv[r0g]; d20 = di * di; }
        if (r1g < nrows) { float di = dinv[r1g]; d21 = di * di; }
#pragma unroll
        for (int j = 0; j < NT; j++) {
            int col = j * 8 + (lane & 3) * 2;
            float2 bb = *(const float2*)(bias + col);
            if (r0g < nrows) {
                __half2 hh = __floats2half2_rn(acc[j][0], acc[j][1]);
                *(uint32_t*)(H16 + (size_t)r0g * NCOL + col) = *(uint32_t*)&hh;
                *(float2*)(OUT + (size_t)r0g * NCOL + col) =
                    make_float2(fmaf(acc[j][0], d20, bb.x), fmaf(acc[j][1], d20, bb.y));
            }
            if (r1g < nrows) {
                __half2 hh = __floats2half2_rn(acc[j][2], acc[j][3]);
                *(uint32_t*)(H16 + (size_t)r1g * NCOL + col) = *(uint32_t*)&hh;
                *(float2*)(OUT + (size_t)r1g * NCOL + col) =
                    make_float2(fmaf(acc[j][2], d21, bb.x), fmaf(acc[j][3], d21, bb.y));
            }
        }
    }
}

// ---------------- CSR aggregation: OUT[n] += sum_{e in row n} fp16(H[src_e]) * nrm_e ----------------
__global__ void __launch_bounds__(256) k_agg128(
    const uint16_t* __restrict__ H16, float* __restrict__ OUT, int N)
{
    int gw   = (blockIdx.x * 256 + threadIdx.x) >> 5;
    int lane = threadIdx.x & 31;
    if (gw >= N) return;
    int beg = g_rowptr[gw], end = g_rowptr[gw + 1];
    if (beg == end) return;

    const uint16_t* Hl = H16 + lane * 4;
    unsigned long long a0 = 0ull, a1 = 0ull;
    int j = beg;
    for (; j + 4 <= end; j += 4) {
        float2 e0 = g_csr[j];
        float2 e1 = g_csr[j + 1];
        float2 e2 = g_csr[j + 2];
        float2 e3 = g_csr[j + 3];
        uint2 v0 = *(const uint2*)(Hl + (size_t)__float_as_int(e0.x) * 128);
        uint2 v1 = *(const uint2*)(Hl + (size_t)__float_as_int(e1.x) * 128);
        uint2 v2 = *(const uint2*)(Hl + (size_t)__float_as_int(e2.x) * 128);
        uint2 v3 = *(const uint2*)(Hl + (size_t)__float_as_int(e3.x) * 128);
        fma_h4(a0, a1, v0, packdup(e0.y));
        fma_h4(a0, a1, v1, packdup(e1.y));
        fma_h4(a0, a1, v2, packdup(e2.y));
        fma_h4(a0, a1, v3, packdup(e3.y));
    }
    for (; j < end; j++) {
        float2 e0 = g_csr[j];
        uint2 v0 = *(const uint2*)(Hl + (size_t)__float_as_int(e0.x) * 128);
        fma_h4(a0, a1, v0, packdup(e0.y));
    }
    ulonglong2* op = (ulonglong2*)(OUT + (size_t)gw * 128 + lane * 4);
    ulonglong2 ob = *op;
    ob.x = add2(ob.x, a0);
    ob.y = add2(ob.y, a1);
    *op = ob;
}

__global__ void __launch_bounds__(256) k_agg64(
    const uint16_t* __restrict__ H16, float* __restrict__ OUT, int N)
{
    int idx  = blockIdx.x * 256 + threadIdx.x;
    int node = idx >> 4;
    int lane = idx & 15;
    if (node >= N) return;
    int beg = g_rowptr[node], end = g_rowptr[node + 1];
    if (beg == end) return;

    const uint16_t* Hl = H16 + lane * 4;
    unsigned long long a0 = 0ull, a1 = 0ull;
    int j = beg;
    for (; j + 4 <= end; j += 4) {
        float2 e0 = g_csr[j];
        float2 e1 = g_csr[j + 1];
        float2 e2 = g_csr[j + 2];
        float2 e3 = g_csr[j + 3];
        uint2 v0 = *(const uint2*)(Hl + (size_t)__float_as_int(e0.x) * 64);
        uint2 v1 = *(const uint2*)(Hl + (size_t)__float_as_int(e1.x) * 64);
        uint2 v2 = *(const uint2*)(Hl + (size_t)__float_as_int(e2.x) * 64);
        uint2 v3 = *(const uint2*)(Hl + (size_t)__float_as_int(e3.x) * 64);
        fma_h4(a0, a1, v0, packdup(e0.y));
        fma_h4(a0, a1, v1, packdup(e1.y));
        fma_h4(a0, a1, v2, packdup(e2.y));
        fma_h4(a0, a1, v3, packdup(e3.y));
    }
    for (; j < end; j++) {
        float2 e0 = g_csr[j];
        uint2 v0 = *(const uint2*)(Hl + (size_t)__float_as_int(e0.x) * 64);
        fma_h4(a0, a1, v0, packdup(e0.y));
    }
    ulonglong2* op = (ulonglong2*)(OUT + (size_t)node * 64 + lane * 4);
    ulonglong2 ob = *op;
    ob.x = add2(ob.x, a0);
    ob.y = add2(ob.y, a1);
    *op = ob;
}

// ---------------- launch ----------------
extern "C" void kernel_launch(void* const* d_in, const int* in_sizes, int n_in,
                              void* d_out, int out_size)
{
    const float* x  = (const float*)d_in[0];
    const int*   ei = (const int*)d_in[1];
    const float* W1 = (const float*)d_in[2];
    const float* b1 = (const float*)d_in[3];
    const float* W2 = (const float*)d_in[4];
    const float* b2 = (const float*)d_in[5];
    float*       out = (float*)d_out;

    const int N = in_sizes[0] / 128;   // 50000
    const int E = in_sizes[1] / 2;     // 800000

    float* dinv;   cudaGetSymbolAddress((void**)&dinv, g_dinv);
    uint16_t* h1;  cudaGetSymbolAddress((void**)&h1,   g_h1);
    float* buf1;   cudaGetSymbolAddress((void**)&buf1, g_buf1);
    uint16_t* h2;  cudaGetSymbolAddress((void**)&h2,   g_h2);

    const int SM1 = (2 * 128 * 136 + 2 * 128 * 136) * 2;  // 139264
    const int SM2 = (2 * 128 * 136 + 2 * 128 * 72) * 2;   // 106496
    cudaFuncSetAttribute((const void*)k_gemm_mma<128, false>,
                         cudaFuncAttributeMaxDynamicSharedMemorySize, SM1);
    cudaFuncSetAttribute((const void*)k_gemm_mma<64, true>,
                         cudaFuncAttributeMaxDynamicSharedMemorySize, SM2);

    const int nblkN = (N + 255) / 256;   // 196 (<= 256; co-resident for scan)
    const int nblkE = (E + 255) / 256;

    // CSR build + weight split (deg count fused with W conversion)
    k_count_conv<<<nblkE, 256>>>(ei, E, W1, W2);
    k_scan_all<<<nblkN, 256>>>(N, nblkN);
    k_scatter<<<nblkE, 256>>>(ei, E);

    // layer 1: h1 = fp16(x@W1) ; buf1 = b1 + (x@W1)*dinv^2 (self-loop fused, fp32)
    int gblocks = (N + 127) / 128;   // 391
    k_gemm_mma<128, false><<<gblocks, 256, SM1>>>(x, b1, dinv, h1, buf1, N);
    k_agg128<<<(N * 32 + 255) / 256, 256>>>(h1, buf1, N);

    // layer 2: h2 = fp16(relu(buf1)@W2) ; out = b2 + (relu(buf1)@W2)*dinv^2
    k_gemm_mma<64, true><<<gblocks, 256, SM2>>>(buf1, b2, dinv, h2, out, N);
    k_agg64<<<(N * 16 + 255) / 256, 256>>>(h2, out, N);
}

// round 13
// speedup vs baseline: 1.0301x; 1.0301x over previous
#include <cuda_runtime.h>
#include <cuda_bf16.h>
#include <cuda_fp16.h>
#include <cstdint>

#define MAXN 50000
#define MAXE 800000
#define K_DIM 128

// ---------------- scratch (__device__ globals; no allocs allowed) ----------------
__device__ float  g_dinv[MAXN];
__device__ int    g_deg[MAXN];
__device__ int    g_rowptr[MAXN + 1];
__device__ int    g_cursor[MAXN];
__device__ int    g_bsum[256];
__device__ int    g_boff[256];
__device__ int    g_arrive;
__device__ int    g_flag;
__device__ float2 g_csr[MAXE];
__device__ uint16_t g_h1[(size_t)MAXN * 128];   // fp16 gather buffer (layer 1)
__device__ float    g_buf1[(size_t)MAXN * 128];
__device__ uint16_t g_h2[(size_t)MAXN * 64];    // fp16 gather buffer (layer 2)
// bf16 split weights, plain row-major [k][n]
__device__ uint16_t g_w1h[128 * 128], g_w1l[128 * 128];
__device__ uint16_t g_w2h[128 * 64],  g_w2l[128 * 64];

// ---------------- packed f32x2 helpers (agg path) ----------------
__device__ __forceinline__ unsigned long long packdup(float x) {
    unsigned long long r;
    asm("mov.b64 %0, {%1, %1};" : "=l"(r) : "f"(x));
    return r;
}
__device__ __forceinline__ unsigned long long pack2(float x, float y) {
    unsigned long long r;
    asm("mov.b64 %0, {%1, %2};" : "=l"(r) : "f"(x), "f"(y));
    return r;
}
__device__ __forceinline__ unsigned long long ffma2v(unsigned long long a,
                                                     unsigned long long b,
                                                     unsigned long long c) {
    unsigned long long d;
    asm("fma.rn.f32x2 %0, %1, %2, %3;" : "=l"(d) : "l"(a), "l"(b), "l"(c));
    return d;
}
__device__ __forceinline__ unsigned long long add2(unsigned long long a,
                                                   unsigned long long b) {
    unsigned long long d;
    asm("add.rn.f32x2 %0, %1, %2;" : "=l"(d) : "l"(a), "l"(b));
    return d;
}
// gather 4 fp16 -> two packed f32x2, fma into acc
__device__ __forceinline__ void fma_h4(unsigned long long& a0, unsigned long long& a1,
                                       uint2 v, unsigned long long nrm) {
    float2 f0 = __half22float2(*(__half2*)&v.x);
    float2 f1 = __half22float2(*(__half2*)&v.y);
    a0 = ffma2v(pack2(f0.x, f0.y), nrm, a0);
    a1 = ffma2v(pack2(f1.x, f1.y), nrm, a1);
}

// ---------------- mma / ldmatrix helpers (sm_80-era, valid at compute_103) ----------------
__device__ __forceinline__ uint32_t smem_u32(const void* p) {
    uint32_t a;
    asm("{ .reg .u64 t; cvta.to.shared.u64 t, %1; cvt.u32.u64 %0, t; }"
        : "=r"(a) : "l"(p));
    return a;
}
__device__ __forceinline__ void mma16816(float* d, const uint32_t* a, const uint32_t* b) {
    asm volatile(
        "mma.sync.aligned.m16n8k16.row.col.f32.bf16.bf16.f32 "
        "{%0,%1,%2,%3}, {%4,%5,%6,%7}, {%8,%9}, {%0,%1,%2,%3};"
        : "+f"(d[0]), "+f"(d[1]), "+f"(d[2]), "+f"(d[3])
        : "r"(a[0]), "r"(a[1]), "r"(a[2]), "r"(a[3]), "r"(b[0]), "r"(b[1]));
}
__device__ __forceinline__ void ldsm_x4(uint32_t* r, uint32_t addr) {
    asm volatile("ldmatrix.sync.aligned.m8n8.x4.shared.b16 {%0,%1,%2,%3}, [%4];"
                 : "=r"(r[0]), "=r"(r[1]), "=r"(r[2]), "=r"(r[3]) : "r"(addr));
}
__device__ __forceinline__ void ldsm_x4t(uint32_t* r, uint32_t addr) {
    asm volatile("ldmatrix.sync.aligned.m8n8.x4.trans.shared.b16 {%0,%1,%2,%3}, [%4];"
                 : "=r"(r[0]), "=r"(r[1]), "=r"(r[2]), "=r"(r[3]) : "r"(addr));
}
__device__ __forceinline__ void split_bf16(float x, uint16_t& hi, uint16_t& lo) {
    __nv_bfloat16 h = __float2bfloat16_rn(x);
    __nv_bfloat16 l = __float2bfloat16_rn(x - __bfloat162float(h));
    hi = __bfloat16_as_ushort(h);
    lo = __bfloat16_as_ushort(l);
}

// ---------------- weight split (once per call) ----------------
__global__ void k_convW_all(const float* __restrict__ W1, const float* __restrict__ W2) {
    int idx = blockIdx.x * blockDim.x + threadIdx.x;
    if (idx < 128 * 128) {
        uint16_t h, l;
        split_bf16(W1[idx], h, l);
        g_w1h[idx] = h; g_w1l[idx] = l;
    } else if (idx < 128 * 128 + 128 * 64) {
        int j = idx - 128 * 128;
        uint16_t h, l;
        split_bf16(W2[j], h, l);
        g_w2h[j] = h; g_w2l[j] = l;
    }
}

// ---------------- degree / CSR build ----------------
__global__ void k_zero_deg(int n) {
    int i = blockIdx.x * blockDim.x + threadIdx.x;
    if (i < n) g_deg[i] = 0;
    if (i == 0) { g_arrive = 0; g_flag = 0; }
}

__global__ void k_count_deg(const int* __restrict__ ei, int E) {
    int i = blockIdx.x * blockDim.x + threadIdx.x;
    if (i < E) atomicAdd(&g_deg[ei[E + i]], 1);
}

__global__ void __launch_bounds__(256) k_scan_all(int n, int nb) {
    __shared__ int s[256];
    __shared__ int s_go;
    int t = threadIdx.x, b = blockIdx.x;
    int i = b * 256 + t;
    int v = (i < n) ? g_deg[i] : 0;
    if (i < n) g_dinv[i] = rsqrtf((float)v + 1.0f);
    s[t] = v;
    __syncthreads();
#pragma unroll
    for (int off = 1; off < 256; off <<= 1) {
        int a = (t >= off) ? s[t - off] : 0;
        __syncthreads();
        s[t] += a;
        __syncthreads();
    }
    int incl = s[t];
    if (t == 255) {
        g_bsum[b] = incl;
        __threadfence();
        int tk = atomicAdd(&g_arrive, 1);
        s_go = (tk == nb - 1);
    }
    __syncthreads();
    if (s_go) {
        int bv2 = (t < nb) ? g_bsum[t] : 0;
        s[t] = bv2;
        __syncthreads();
#pragma unroll
        for (int off = 1; off < 256; off <<= 1) {
            int a = (t >= off) ? s[t - off] : 0;
            __syncthreads();
            s[t] += a;
            __syncthreads();
        }
        if (t < nb) g_boff[t] = s[t] - bv2;
        __threadfence();
        if (t == 0) atomicExch(&g_flag, 1);
    } else {
        if (t == 0) { while (atomicAdd(&g_flag, 0) == 0) { } }
        __syncthreads();
    }
    int boff = *((volatile int*)&g_boff[b]);
    if (i < n) {
        int r = incl - v + boff;
        g_rowptr[i] = r;
        g_cursor[i] = r;
        if (i == n - 1) g_rowptr[n] = r + v;
    }
}

__global__ void k_scatter(const int* __restrict__ ei, int E) {
    int e = blockIdx.x * blockDim.x + threadIdx.x;
    if (e < E) {
        int s = ei[e];
        int d = ei[E + e];
        int pos = atomicAdd(&g_cursor[d], 1);
        g_csr[pos] = make_float2(__int_as_float(s), g_dinv[s] * g_dinv[d]);
    }
}

// ---------------- tensor-core GEMM: Hfp16 = X @ W ; OUT = bias + H*dinv^2 ----------------
// 8 warps in 4x2 grid; warp tile 32 rows x NCOL/2 cols (ldsm-balanced).
// 3xBF16 split (hi*hi + hi*lo + lo*hi), fp32 accumulate via mma.sync m16n8k16.
template <int NCOL, bool RELU>
__global__ void __launch_bounds__(256, 1) k_gemm_mma(
    const float* __restrict__ X, const float* __restrict__ bias,
    const float* __restrict__ dinv, uint16_t* __restrict__ H16,
    float* __restrict__ OUT, int nrows)
{
    constexpr int PX  = 136;                        // X pitch (bf16)
    constexpr int PW  = (NCOL == 128) ? 136 : 72;   // W pitch
    constexpr int WC  = NCOL / 2;                   // cols per warp
    constexpr int NPW = WC / 16;                    // b-ldsm pairs per kt (4 or 2)

    extern __shared__ uint16_t sm16[];
    uint16_t* sXh = sm16;
    uint16_t* sXl = sXh + 128 * PX;
    uint16_t* sWh = sXl + 128 * PX;
    uint16_t* sWl = sWh + 128 * PW;

    const int tid  = threadIdx.x;
    const int warp = tid >> 5;
    const int lane = tid & 31;
    const int row0 = blockIdx.x * 128;

    // stage W from pre-split global bf16 [128][NCOL] into padded smem
    {
        const uint4* gh = (const uint4*)((NCOL == 128) ? g_w1h : g_w2h);
        const uint4* gl = (const uint4*)((NCOL == 128) ? g_w1l : g_w2l);
        for (int i = tid; i < 128 * (NCOL / 8); i += 256) {
            int k = i / (NCOL / 8), c = i % (NCOL / 8);
            ((uint4*)(sWh + k * PW))[c] = gh[i];
            ((uint4*)(sWl + k * PW))[c] = gl[i];
        }
    }

    // stage X: thread handles row tid/2, 64-col half tid&1; split to bf16 hi/lo
    {
        int r = tid >> 1, half = tid & 1;
        int row = row0 + r;
        uint32_t* dh = (uint32_t*)(sXh + r * PX + half * 64);
        uint32_t* dl = (uint32_t*)(sXl + r * PX + half * 64);
        if (row < nrows) {
            const float4* xr = (const float4*)(X + (size_t)row * K_DIM) + half * 16;
#pragma unroll 4
            for (int c4 = 0; c4 < 16; c4++) {
                float4 v = xr[c4];
                if (RELU) {
                    v.x = fmaxf(v.x, 0.f); v.y = fmaxf(v.y, 0.f);
                    v.z = fmaxf(v.z, 0.f); v.w = fmaxf(v.w, 0.f);
                }
                uint16_t h0, l0, h1, l1, h2, l2, h3, l3;
                split_bf16(v.x, h0, l0); split_bf16(v.y, h1, l1);
                split_bf16(v.z, h2, l2); split_bf16(v.w, h3, l3);
                dh[2 * c4]     = (uint32_t)h0 | ((uint32_t)h1 << 16);
                dh[2 * c4 + 1] = (uint32_t)h2 | ((uint32_t)h3 << 16);
                dl[2 * c4]     = (uint32_t)l0 | ((uint32_t)l1 << 16);
                dl[2 * c4 + 1] = (uint32_t)l2 | ((uint32_t)l3 << 16);
            }
        } else {
#pragma unroll 4
            for (int c4 = 0; c4 < 16; c4++) {
                dh[2 * c4] = 0u; dh[2 * c4 + 1] = 0u;
                dl[2 * c4] = 0u; dl[2 * c4 + 1] = 0u;
            }
        }
    }
    __syncthreads();

    const uint32_t bXh = smem_u32(sXh), bXl = smem_u32(sXl);
    const uint32_t bWh = smem_u32(sWh), bWl = smem_u32(sWl);

    float acc[2][2 * NPW][4];
#pragma unroll
    for (int rs = 0; rs < 2; rs++)
#pragma unroll
        for (int j = 0; j < 2 * NPW; j++) {
            acc[rs][j][0] = 0.f; acc[rs][j][1] = 0.f;
            acc[rs][j][2] = 0.f; acc[rs][j][3] = 0.f;
        }

    const int wr = warp >> 1, wc = warp & 1;
    const int mrow = wr * 32;
    const uint32_t aoff0 = ((uint32_t)(mrow + (lane & 15)) * PX + ((lane >> 4) << 3)) * 2;
    const uint32_t aoff1 = aoff0 + 16 * PX * 2;
    const uint32_t boff  = ((uint32_t)(lane & 15) * PW + ((lane >> 4) << 3) + wc * WC) * 2;

#pragma unroll
    for (int kt = 0; kt < 8; kt++) {
        uint32_t ah0[4], al0[4], ah1[4], al1[4];
        ldsm_x4(ah0, bXh + aoff0 + kt * 32);
        ldsm_x4(al0, bXl + aoff0 + kt * 32);
        ldsm_x4(ah1, bXh + aoff1 + kt * 32);
        ldsm_x4(al1, bXl + aoff1 + kt * 32);
        uint32_t bk = kt * 16 * PW * 2;
#pragma unroll
        for (int np = 0; np < NPW; np++) {
            uint32_t bh[4], bl[4];
            ldsm_x4t(bh, bWh + boff + bk + np * 32);
            ldsm_x4t(bl, bWl + boff + bk + np * 32);
            mma16816(acc[0][2 * np],     ah0, bh);
            mma16816(acc[0][2 * np + 1], ah0, bh + 2);
            mma16816(acc[0][2 * np],     ah0, bl);
            mma16816(acc[0][2 * np + 1], ah0, bl + 2);
            mma16816(acc[0][2 * np],     al0, bh);
            mma16816(acc[0][2 * np + 1], al0, bh + 2);
            mma16816(acc[1][2 * np],     ah1, bh);
            mma16816(acc[1][2 * np + 1], ah1, bh + 2);
            mma16816(acc[1][2 * np],     ah1, bl);
            mma16816(acc[1][2 * np + 1], ah1, bl + 2);
            mma16816(acc[1][2 * np],     al1, bh);
            mma16816(acc[1][2 * np + 1], al1, bh + 2);
        }
    }

    // epilogue: per rs, thread owns rows (mrow + rs*16 + lane/4) and +8
#pragma unroll
    for (int rs = 0; rs < 2; rs++) {
        int r0g = row0 + mrow + rs * 16 + (lane >> 2);
        int r1g = r0g + 8;
        float d20 = 0.f, d21 = 0.f;
        if (r0g < nrows) { float di = dinv[r0g]; d20 = di * di; }
        if (r1g < nrows) { float di = dinv[r1g]; d21 = di * di; }
#pragma unroll
        for (int j = 0; j < 2 * NPW; j++) {
            int col = wc * WC + j * 8 + (lane & 3) * 2;
            float2 bb = *(const float2*)(bias + col);
            if (r0g < nrows) {
                __half2 hh = __floats2half2_rn(acc[rs][j][0], acc[rs][j][1]);
                *(uint32_t*)(H16 + (size_t)r0g * NCOL + col) = *(uint32_t*)&hh;
                *(float2*)(OUT + (size_t)r0g * NCOL + col) =
                    make_float2(fmaf(acc[rs][j][0], d20, bb.x),
                                fmaf(acc[rs][j][1], d20, bb.y));
            }
            if (r1g < nrows) {
                __half2 hh = __floats2half2_rn(acc[rs][j][2], acc[rs][j][3]);
                *(uint32_t*)(H16 + (size_t)r1g * NCOL + col) = *(uint32_t*)&hh;
                *(float2*)(OUT + (size_t)r1g * NCOL + col) =
                    make_float2(fmaf(acc[rs][j][2], d21, bb.x),
                                fmaf(acc[rs][j][3], d21, bb.y));
            }
        }
    }
}

// ---------------- CSR aggregation: OUT[n] += sum_{e in row n} fp16(H[src_e]) * nrm_e ----------------
__global__ void __launch_bounds__(256) k_agg128(
    const uint16_t* __restrict__ H16, float* __restrict__ OUT, int N)
{
    int gw   = (blockIdx.x * 256 + threadIdx.x) >> 5;
    int lane = threadIdx.x & 31;
    if (gw >= N) return;
    int beg = g_rowptr[gw], end = g_rowptr[gw + 1];
    if (beg == end) return;

    const uint16_t* Hl = H16 + lane * 4;
    unsigned long long a0 = 0ull, a1 = 0ull;
    int j = beg;
    for (; j + 2 <= end; j += 2) {
        float2 e0 = g_csr[j];
        float2 e1 = g_csr[j + 1];
        uint2 v0 = *(const uint2*)(Hl + (size_t)__float_as_int(e0.x) * 128);
        uint2 v1 = *(const uint2*)(Hl + (size_t)__float_as_int(e1.x) * 128);
        fma_h4(a0, a1, v0, packdup(e0.y));
        fma_h4(a0, a1, v1, packdup(e1.y));
    }
    if (j < end) {
        float2 e0 = g_csr[j];
        uint2 v0 = *(const uint2*)(Hl + (size_t)__float_as_int(e0.x) * 128);
        fma_h4(a0, a1, v0, packdup(e0.y));
    }
    ulonglong2* op = (ulonglong2*)(OUT + (size_t)gw * 128 + lane * 4);
    ulonglong2 ob = *op;
    ob.x = add2(ob.x, a0);
    ob.y = add2(ob.y, a1);
    *op = ob;
}

__global__ void __launch_bounds__(256) k_agg64(
    const uint16_t* __restrict__ H16, float* __restrict__ OUT, int N)
{
    int idx  = blockIdx.x * 256 + threadIdx.x;
    int node = idx >> 4;
    int lane = idx & 15;
    if (node >= N) return;
    int beg = g_rowptr[node], end = g_rowptr[node + 1];
    if (beg == end) return;

    const uint16_t* Hl = H16 + lane * 4;
    unsigned long long a0 = 0ull, a1 = 0ull;
    int j = beg;
    for (; j + 2 <= end; j += 2) {
        float2 e0 = g_csr[j];
        float2 e1 = g_csr[j + 1];
        uint2 v0 = *(const uint2*)(Hl + (size_t)__float_as_int(e0.x) * 64);
        uint2 v1 = *(const uint2*)(Hl + (size_t)__float_as_int(e1.x) * 64);
        fma_h4(a0, a1, v0, packdup(e0.y));
        fma_h4(a0, a1, v1, packdup(e1.y));
    }
    if (j < end) {
        float2 e0 = g_csr[j];
        uint2 v0 = *(const uint2*)(Hl + (size_t)__float_as_int(e0.x) * 64);
        fma_h4(a0, a1, v0, packdup(e0.y));
    }
    ulonglong2* op = (ulonglong2*)(OUT + (size_t)node * 64 + lane * 4);
    ulonglong2 ob = *op;
    ob.x = add2(ob.x, a0);
    ob.y = add2(ob.y, a1);
    *op = ob;
}

// ---------------- launch ----------------
extern "C" void kernel_launch(void* const* d_in, const int* in_sizes, int n_in,
                              void* d_out, int out_size)
{
    const float* x  = (const float*)d_in[0];
    const int*   ei = (const int*)d_in[1];
    const float* W1 = (const float*)d_in[2];
    const float* b1 = (const float*)d_in[3];
    const float* W2 = (const float*)d_in[4];
    const float* b2 = (const float*)d_in[5];
    float*       out = (float*)d_out;

    const int N = in_sizes[0] / 128;   // 50000
    const int E = in_sizes[1] / 2;     // 800000

    float* dinv;   cudaGetSymbolAddress((void**)&dinv, g_dinv);
    uint16_t* h1;  cudaGetSymbolAddress((void**)&h1,   g_h1);
    float* buf1;   cudaGetSymbolAddress((void**)&buf1, g_buf1);
    uint16_t* h2;  cudaGetSymbolAddress((void**)&h2,   g_h2);

    const int SM1 = (2 * 128 * 136 + 2 * 128 * 136) * 2;  // 139264
    const int SM2 = (2 * 128 * 136 + 2 * 128 * 72) * 2;   // 106496
    cudaFuncSetAttribute((const void*)k_gemm_mma<128, false>,
                         cudaFuncAttributeMaxDynamicSharedMemorySize, SM1);
    cudaFuncSetAttribute((const void*)k_gemm_mma<64, true>,
                         cudaFuncAttributeMaxDynamicSharedMemorySize, SM2);

    const int nblkN = (N + 255) / 256;
    const int nblkE = (E + 255) / 256;

    // weight bf16 split (once per call)
    k_convW_all<<<(128 * 128 + 128 * 64 + 255) / 256, 256>>>(W1, W2);

    // CSR build
    k_zero_deg<<<nblkN, 256>>>(N);
    k_count_deg<<<nblkE, 256>>>(ei, E);
    k_scan_all<<<nblkN, 256>>>(N, nblkN);
    k_scatter<<<nblkE, 256>>>(ei, E);

    // layer 1: h1 = fp16(x@W1) ; buf1 = b1 + (x@W1)*dinv^2 (self-loop fused, fp32)
    int gblocks = (N + 127) / 128;   // 391
    k_gemm_mma<128, false><<<gblocks, 256, SM1>>>(x, b1, dinv, h1, buf1, N);
    k_agg128<<<(N * 32 + 255) / 256, 256>>>(h1, buf1, N);

    // layer 2: h2 = fp16(relu(buf1)@W2) ; out = b2 + (relu(buf1)@W2)*dinv^2
    k_gemm_mma<64, true><<<gblocks, 256, SM2>>>(buf1, b2, dinv, h2, out, N);
    k_agg64<<<(N * 16 + 255) / 256, 256>>>(h2, out, N);
}

// round 14
// speedup vs baseline: 1.1109x; 1.0785x over previous
#include <cuda_runtime.h>
#include <cuda_bf16.h>
#include <cuda_fp16.h>
#include <cstdint>

#define MAXN 50000
#define MAXE 800000
#define K_DIM 128

// ---------------- scratch (__device__ globals; no allocs allowed) ----------------
__device__ float  g_dinv[MAXN];
__device__ int    g_deg[MAXN];
__device__ int    g_rowptr[MAXN + 1];
__device__ int    g_cursor[MAXN];
__device__ int    g_bsum[256];
__device__ int    g_boff[256];
__device__ int    g_arrive;
__device__ int    g_flag;
__device__ float2 g_csr[MAXE];
__device__ uint16_t g_h1[(size_t)MAXN * 128];   // fp16 gather buffer (layer 1)
__device__ float    g_buf1[(size_t)MAXN * 128];
__device__ uint16_t g_h2[(size_t)MAXN * 64];    // fp16 gather buffer (layer 2)

// ---------------- packed f32x2 helpers (agg path) ----------------
__device__ __forceinline__ unsigned long long packdup(float x) {
    unsigned long long r;
    asm("mov.b64 %0, {%1, %1};" : "=l"(r) : "f"(x));
    return r;
}
__device__ __forceinline__ unsigned long long pack2(float x, float y) {
    unsigned long long r;
    asm("mov.b64 %0, {%1, %2};" : "=l"(r) : "f"(x), "f"(y));
    return r;
}
__device__ __forceinline__ unsigned long long ffma2v(unsigned long long a,
                                                     unsigned long long b,
                                                     unsigned long long c) {
    unsigned long long d;
    asm("fma.rn.f32x2 %0, %1, %2, %3;" : "=l"(d) : "l"(a), "l"(b), "l"(c));
    return d;
}
__device__ __forceinline__ unsigned long long add2(unsigned long long a,
                                                   unsigned long long b) {
    unsigned long long d;
    asm("add.rn.f32x2 %0, %1, %2;" : "=l"(d) : "l"(a), "l"(b));
    return d;
}
// gather 4 fp16 -> two packed f32x2, fma into acc
__device__ __forceinline__ void fma_h4(unsigned long long& a0, unsigned long long& a1,
                                       uint2 v, unsigned long long nrm) {
    float2 f0 = __half22float2(*(__half2*)&v.x);
    float2 f1 = __half22float2(*(__half2*)&v.y);
    a0 = ffma2v(pack2(f0.x, f0.y), nrm, a0);
    a1 = ffma2v(pack2(f1.x, f1.y), nrm, a1);
}

// ---------------- mma / ldmatrix helpers (sm_80-era, valid at compute_103) ----------------
__device__ __forceinline__ uint32_t smem_u32(const void* p) {
    uint32_t a;
    asm("{ .reg .u64 t; cvta.to.shared.u64 t, %1; cvt.u32.u64 %0, t; }"
        : "=r"(a) : "l"(p));
    return a;
}
__device__ __forceinline__ void mma16816(float* d, const uint32_t* a, const uint32_t* b) {
    asm volatile(
        "mma.sync.aligned.m16n8k16.row.col.f32.bf16.bf16.f32 "
        "{%0,%1,%2,%3}, {%4,%5,%6,%7}, {%8,%9}, {%0,%1,%2,%3};"
        : "+f"(d[0]), "+f"(d[1]), "+f"(d[2]), "+f"(d[3])
        : "r"(a[0]), "r"(a[1]), "r"(a[2]), "r"(a[3]), "r"(b[0]), "r"(b[1]));
}
__device__ __forceinline__ void ldsm_x4(uint32_t* r, uint32_t addr) {
    asm volatile("ldmatrix.sync.aligned.m8n8.x4.shared.b16 {%0,%1,%2,%3}, [%4];"
                 : "=r"(r[0]), "=r"(r[1]), "=r"(r[2]), "=r"(r[3]) : "r"(addr));
}
__device__ __forceinline__ void ldsm_x4t(uint32_t* r, uint32_t addr) {
    asm volatile("ldmatrix.sync.aligned.m8n8.x4.trans.shared.b16 {%0,%1,%2,%3}, [%4];"
                 : "=r"(r[0]), "=r"(r[1]), "=r"(r[2]), "=r"(r[3]) : "r"(addr));
}
__device__ __forceinline__ void split_bf16(float x, uint16_t& hi, uint16_t& lo) {
    __nv_bfloat16 h = __float2bfloat16_rn(x);
    __nv_bfloat16 l = __float2bfloat16_rn(x - __bfloat162float(h));
    hi = __bfloat16_as_ushort(h);
    lo = __bfloat16_as_ushort(l);
}

// ---------------- degree / CSR build ----------------
__global__ void k_zero_deg(int n) {
    int i = blockIdx.x * blockDim.x + threadIdx.x;
    if (i < n) g_deg[i] = 0;
    if (i == 0) { g_arrive = 0; g_flag = 0; }
}

__global__ void k_count_deg(const int* __restrict__ ei, int E) {
    int i = blockIdx.x * blockDim.x + threadIdx.x;
    if (i < E) atomicAdd(&g_deg[ei[E + i]], 1);
}

__global__ void __launch_bounds__(256) k_scan_all(int n, int nb) {
    __shared__ int s[256];
    __shared__ int s_go;
    int t = threadIdx.x, b = blockIdx.x;
    int i = b * 256 + t;
    int v = (i < n) ? g_deg[i] : 0;
    if (i < n) g_dinv[i] = rsqrtf((float)v + 1.0f);
    s[t] = v;
    __syncthreads();
#pragma unroll
    for (int off = 1; off < 256; off <<= 1) {
        int a = (t >= off) ? s[t - off] : 0;
        __syncthreads();
        s[t] += a;
        __syncthreads();
    }
    int incl = s[t];
    if (t == 255) {
        g_bsum[b] = incl;
        __threadfence();
        int tk = atomicAdd(&g_arrive, 1);
        s_go = (tk == nb - 1);
    }
    __syncthreads();
    if (s_go) {
        int bv2 = (t < nb) ? g_bsum[t] : 0;
        s[t] = bv2;
        __syncthreads();
#pragma unroll
        for (int off = 1; off < 256; off <<= 1) {
            int a = (t >= off) ? s[t - off] : 0;
            __syncthreads();
            s[t] += a;
            __syncthreads();
        }
        if (t < nb) g_boff[t] = s[t] - bv2;
        __threadfence();
        if (t == 0) atomicExch(&g_flag, 1);
    } else {
        if (t == 0) { while (atomicAdd(&g_flag, 0) == 0) { } }
        __syncthreads();
    }
    int boff = *((volatile int*)&g_boff[b]);
    if (i < n) {
        int r = incl - v + boff;
        g_rowptr[i] = r;
        g_cursor[i] = r;
        if (i == n - 1) g_rowptr[n] = r + v;
    }
}

__global__ void k_scatter(const int* __restrict__ ei, int E) {
    int e = blockIdx.x * blockDim.x + threadIdx.x;
    if (e < E) {
        int s = ei[e];
        int d = ei[E + e];
        int pos = atomicAdd(&g_cursor[d], 1);
        g_csr[pos] = make_float2(__int_as_float(s), g_dinv[s] * g_dinv[d]);
    }
}

// ---------------- tensor-core GEMM: Hfp16 = X @ W (no epilogue; W split in-kernel) ----------------
// 8 warps in 4x2 grid; warp tile 32 rows x NCOL/2 cols.
// 3xBF16 split (hi*hi + hi*lo + lo*hi), fp32 accumulate via mma.sync m16n8k16.
template <int NCOL, bool RELU>
__global__ void __launch_bounds__(256, 1) k_gemm_mma(
    const float* __restrict__ X, const float* __restrict__ W,
    uint16_t* __restrict__ H16, int nrows)
{
    constexpr int PX  = 136;                        // X pitch (bf16)
    constexpr int PW  = (NCOL == 128) ? 136 : 72;   // W pitch
    constexpr int WC  = NCOL / 2;                   // cols per warp
    constexpr int NPW = WC / 16;                    // b-ldsm pairs per kt

    extern __shared__ uint16_t sm16[];
    uint16_t* sXh = sm16;
    uint16_t* sXl = sXh + 128 * PX;
    uint16_t* sWh = sXl + 128 * PX;
    uint16_t* sWl = sWh + 128 * PW;

    const int tid  = threadIdx.x;
    const int warp = tid >> 5;
    const int lane = tid & 31;
    const int row0 = blockIdx.x * 128;

    // stage W: load fp32, split to bf16 hi/lo in-kernel (W is L2-hot)
    for (int i = tid; i < 128 * NCOL / 4; i += 256) {
        float4 w = ((const float4*)W)[i];
        int k = (4 * i) / NCOL, c = (4 * i) % NCOL;
        uint16_t h0, l0, h1, l1, h2, l2, h3, l3;
        split_bf16(w.x, h0, l0); split_bf16(w.y, h1, l1);
        split_bf16(w.z, h2, l2); split_bf16(w.w, h3, l3);
        *(uint32_t*)(sWh + k * PW + c)     = (uint32_t)h0 | ((uint32_t)h1 << 16);
        *(uint32_t*)(sWh + k * PW + c + 2) = (uint32_t)h2 | ((uint32_t)h3 << 16);
        *(uint32_t*)(sWl + k * PW + c)     = (uint32_t)l0 | ((uint32_t)l1 << 16);
        *(uint32_t*)(sWl + k * PW + c + 2) = (uint32_t)l2 | ((uint32_t)l3 << 16);
    }

    // stage X: thread handles row tid/2, 64-col half tid&1; split to bf16 hi/lo
    {
        int r = tid >> 1, half = tid & 1;
        int row = row0 + r;
        uint32_t* dh = (uint32_t*)(sXh + r * PX + half * 64);
        uint32_t* dl = (uint32_t*)(sXl + r * PX + half * 64);
        if (row < nrows) {
            const float4* xr = (const float4*)(X + (size_t)row * K_DIM) + half * 16;
#pragma unroll 4
            for (int c4 = 0; c4 < 16; c4++) {
                float4 v = xr[c4];
                if (RELU) {
                    v.x = fmaxf(v.x, 0.f); v.y = fmaxf(v.y, 0.f);
                    v.z = fmaxf(v.z, 0.f); v.w = fmaxf(v.w, 0.f);
                }
                uint16_t h0, l0, h1, l1, h2, l2, h3, l3;
                split_bf16(v.x, h0, l0); split_bf16(v.y, h1, l1);
                split_bf16(v.z, h2, l2); split_bf16(v.w, h3, l3);
                dh[2 * c4]     = (uint32_t)h0 | ((uint32_t)h1 << 16);
                dh[2 * c4 + 1] = (uint32_t)h2 | ((uint32_t)h3 << 16);
                dl[2 * c4]     = (uint32_t)l0 | ((uint32_t)l1 << 16);
                dl[2 * c4 + 1] = (uint32_t)l2 | ((uint32_t)l3 << 16);
            }
        } else {
#pragma unroll 4
            for (int c4 = 0; c4 < 16; c4++) {
                dh[2 * c4] = 0u; dh[2 * c4 + 1] = 0u;
                dl[2 * c4] = 0u; dl[2 * c4 + 1] = 0u;
            }
        }
    }
    __syncthreads();

    const uint32_t bXh = smem_u32(sXh), bXl = smem_u32(sXl);
    const uint32_t bWh = smem_u32(sWh), bWl = smem_u32(sWl);

    float acc[2][2 * NPW][4];
#pragma unroll
    for (int rs = 0; rs < 2; rs++)
#pragma unroll
        for (int j = 0; j < 2 * NPW; j++) {
            acc[rs][j][0] = 0.f; acc[rs][j][1] = 0.f;
            acc[rs][j][2] = 0.f; acc[rs][j][3] = 0.f;
        }

    const int wr = warp >> 1, wc = warp & 1;
    const int mrow = wr * 32;
    const uint32_t aoff0 = ((uint32_t)(mrow + (lane & 15)) * PX + ((lane >> 4) << 3)) * 2;
    const uint32_t aoff1 = aoff0 + 16 * PX * 2;
    const uint32_t boff  = ((uint32_t)(lane & 15) * PW + ((lane >> 4) << 3) + wc * WC) * 2;

#pragma unroll
    for (int kt = 0; kt < 8; kt++) {
        uint32_t ah0[4], al0[4], ah1[4], al1[4];
        ldsm_x4(ah0, bXh + aoff0 + kt * 32);
        ldsm_x4(al0, bXl + aoff0 + kt * 32);
        ldsm_x4(ah1, bXh + aoff1 + kt * 32);
        ldsm_x4(al1, bXl + aoff1 + kt * 32);
        uint32_t bk = kt * 16 * PW * 2;
#pragma unroll
        for (int np = 0; np < NPW; np++) {
            uint32_t bh[4], bl[4];
            ldsm_x4t(bh, bWh + boff + bk + np * 32);
            ldsm_x4t(bl, bWl + boff + bk + np * 32);
            mma16816(acc[0][2 * np],     ah0, bh);
            mma16816(acc[0][2 * np + 1], ah0, bh + 2);
            mma16816(acc[0][2 * np],     ah0, bl);
            mma16816(acc[0][2 * np + 1], ah0, bl + 2);
            mma16816(acc[0][2 * np],     al0, bh);
            mma16816(acc[0][2 * np + 1], al0, bh + 2);
            mma16816(acc[1][2 * np],     ah1, bh);
            mma16816(acc[1][2 * np + 1], ah1, bh + 2);
            mma16816(acc[1][2 * np],     ah1, bl);
            mma16816(acc[1][2 * np + 1], ah1, bl + 2);
            mma16816(acc[1][2 * np],     al1, bh);
            mma16816(acc[1][2 * np + 1], al1, bh + 2);
        }
    }

    // epilogue: fp16 H only (bias/dinv/self-loop handled by the agg kernels)
#pragma unroll
    for (int rs = 0; rs < 2; rs++) {
        int r0g = row0 + mrow + rs * 16 + (lane >> 2);
        int r1g = r0g + 8;
#pragma unroll
        for (int j = 0; j < 2 * NPW; j++) {
            int col = wc * WC + j * 8 + (lane & 3) * 2;
            if (r0g < nrows) {
                __half2 hh = __floats2half2_rn(acc[rs][j][0], acc[rs][j][1]);
                *(uint32_t*)(H16 + (size_t)r0g * NCOL + col) = *(uint32_t*)&hh;
            }
            if (r1g < nrows) {
                __half2 hh = __floats2half2_rn(acc[rs][j][2], acc[rs][j][3]);
                *(uint32_t*)(H16 + (size_t)r1g * NCOL + col) = *(uint32_t*)&hh;
            }
        }
    }
}

// ---------------- CSR aggregation: OUT[n] = bias + dinv^2*H[n] + sum_e H[src_e]*nrm_e ----------------
__global__ void __launch_bounds__(256) k_agg128(
    const uint16_t* __restrict__ H16, const float* __restrict__ bias,
    const float* __restrict__ dinv, float* __restrict__ OUT, int N)
{
    int gw   = (blockIdx.x * 256 + threadIdx.x) >> 5;
    int lane = threadIdx.x & 31;
    if (gw >= N) return;
    int beg = g_rowptr[gw], end = g_rowptr[gw + 1];

    const uint16_t* Hl = H16 + lane * 4;
    unsigned long long a0 = 0ull, a1 = 0ull;
    int j = beg;
    for (; j + 2 <= end; j += 2) {
        float2 e0 = g_csr[j];
        float2 e1 = g_csr[j + 1];
        uint2 v0 = *(const uint2*)(Hl + (size_t)__float_as_int(e0.x) * 128);
        uint2 v1 = *(const uint2*)(Hl + (size_t)__float_as_int(e1.x) * 128);
        fma_h4(a0, a1, v0, packdup(e0.y));
        fma_h4(a0, a1, v1, packdup(e1.y));
    }
    if (j < end) {
        float2 e0 = g_csr[j];
        uint2 v0 = *(const uint2*)(Hl + (size_t)__float_as_int(e0.x) * 128);
        fma_h4(a0, a1, v0, packdup(e0.y));
    }

    float di = dinv[gw];
    unsigned long long d2 = packdup(di * di);
    uint2 sv = *(const uint2*)(Hl + (size_t)gw * 128);
    float2 s0 = __half22float2(*(__half2*)&sv.x);
    float2 s1 = __half22float2(*(__half2*)&sv.y);
    float2 b0 = *(const float2*)(bias + lane * 4);
    float2 b1 = *(const float2*)(bias + lane * 4 + 2);
    ulonglong2 ob;
    ob.x = ffma2v(pack2(s0.x, s0.y), d2, add2(pack2(b0.x, b0.y), a0));
    ob.y = ffma2v(pack2(s1.x, s1.y), d2, add2(pack2(b1.x, b1.y), a1));
    *(ulonglong2*)(OUT + (size_t)gw * 128 + lane * 4) = ob;
}

__global__ void __launch_bounds__(256) k_agg64(
    const uint16_t* __restrict__ H16, const float* __restrict__ bias,
    const float* __restrict__ dinv, float* __restrict__ OUT, int N)
{
    int idx  = blockIdx.x * 256 + threadIdx.x;
    int node = idx >> 4;
    int lane = idx & 15;
    if (node >= N) return;
    int beg = g_rowptr[node], end = g_rowptr[node + 1];

    const uint16_t* Hl = H16 + lane * 4;
    unsigned long long a0 = 0ull, a1 = 0ull;
    int j = beg;
    for (; j + 2 <= end; j += 2) {
        float2 e0 = g_csr[j];
        float2 e1 = g_csr[j + 1];
        uint2 v0 = *(const uint2*)(Hl + (size_t)__float_as_int(e0.x) * 64);
        uint2 v1 = *(const uint2*)(Hl + (size_t)__float_as_int(e1.x) * 64);
        fma_h4(a0, a1, v0, packdup(e0.y));
        fma_h4(a0, a1, v1, packdup(e1.y));
    }
    if (j < end) {
        float2 e0 = g_csr[j];
        uint2 v0 = *(const uint2*)(Hl + (size_t)__float_as_int(e0.x) * 64);
        fma_h4(a0, a1, v0, packdup(e0.y));
    }

    float di = dinv[node];
    unsigned long long d2 = packdup(di * di);
    uint2 sv = *(const uint2*)(Hl + (size_t)node * 64);
    float2 s0 = __half22float2(*(__half2*)&sv.x);
    float2 s1 = __half22float2(*(__half2*)&sv.y);
    float2 b0 = *(const float2*)(bias + lane * 4);
    float2 b1 = *(const float2*)(bias + lane * 4 + 2);
    ulonglong2 ob;
    ob.x = ffma2v(pack2(s0.x, s0.y), d2, add2(pack2(b0.x, b0.y), a0));
    ob.y = ffma2v(pack2(s1.x, s1.y), d2, add2(pack2(b1.x, b1.y), a1));
    *(ulonglong2*)(OUT + (size_t)node * 64 + lane * 4) = ob;
}

// ---------------- launch ----------------
extern "C" void kernel_launch(void* const* d_in, const int* in_sizes, int n_in,
                              void* d_out, int out_size)
{
    const float* x  = (const float*)d_in[0];
    const int*   ei = (const int*)d_in[1];
    const float* W1 = (const float*)d_in[2];
    const float* b1 = (const float*)d_in[3];
    const float* W2 = (const float*)d_in[4];
    const float* b2 = (const float*)d_in[5];
    float*       out = (float*)d_out;

    const int N = in_sizes[0] / 128;   // 50000
    const int E = in_sizes[1] / 2;     // 800000

    float* dinv;   cudaGetSymbolAddress((void**)&dinv, g_dinv);
    uint16_t* h1;  cudaGetSymbolAddress((void**)&h1,   g_h1);
    float* buf1;   cudaGetSymbolAddress((void**)&buf1, g_buf1);
    uint16_t* h2;  cudaGetSymbolAddress((void**)&h2,   g_h2);

    const int SM1 = (2 * 128 * 136 + 2 * 128 * 136) * 2;  // 139264
    const int SM2 = (2 * 128 * 136 + 2 * 128 * 72) * 2;   // 106496
    cudaFuncSetAttribute((const void*)k_gemm_mma<128, false>,
                         cudaFuncAttributeMaxDynamicSharedMemorySize, SM1);
    cudaFuncSetAttribute((const void*)k_gemm_mma<64, true>,
                         cudaFuncAttributeMaxDynamicSharedMemorySize, SM2);

    // persistent side stream + fork/join events (host objects only; device work
    // is identical on every call -> graph-capture deterministic)
    static cudaStream_t s_bld = nullptr;
    static cudaEvent_t  e_fork = nullptr, e_join = nullptr;
    if (s_bld == nullptr) {
        cudaStreamCreateWithFlags(&s_bld, cudaStreamNonBlocking);
        cudaEventCreateWithFlags(&e_fork, cudaEventDisableTiming);
        cudaEventCreateWithFlags(&e_join, cudaEventDisableTiming);
    }

    const int nblkN = (N + 255) / 256;   // 196 (<= 256; co-resident for scan)
    const int nblkE = (E + 255) / 256;
    const int gblocks = (N + 127) / 128; // 391

    // fork: CSR build on side stream, GEMM1 on main stream (independent)
    cudaEventRecord(e_fork, 0);
    cudaStreamWaitEvent(s_bld, e_fork, 0);
    k_zero_deg<<<nblkN, 256, 0, s_bld>>>(N);
    k_count_deg<<<nblkE, 256, 0, s_bld>>>(ei, E);
    k_scan_all<<<nblkN, 256, 0, s_bld>>>(N, nblkN);
    k_scatter<<<nblkE, 256, 0, s_bld>>>(ei, E);
    cudaEventRecord(e_join, s_bld);

    k_gemm_mma<128, false><<<gblocks, 256, SM1>>>(x, W1, h1, N);

    // join: agg needs both h1 (main) and csr/dinv (side)
    cudaStreamWaitEvent(0, e_join, 0);
    k_agg128<<<(N * 32 + 255) / 256, 256>>>(h1, b1, dinv, buf1, N);

    k_gemm_mma<64, true><<<gblocks, 256, SM2>>>(buf1, W2, h2, N);
    k_agg64<<<(N * 16 + 255) / 256, 256>>>(h2, b2, dinv, out, N);
}

// round 16
// speedup vs baseline: 1.1793x; 1.0615x over previous
#include <cuda_runtime.h>
#include <cuda_bf16.h>
#include <cuda_fp16.h>
#include <cstdint>

#define MAXN 50000
#define MAXE 800000
#define K_DIM 128

// ---------------- scratch (__device__ globals; no allocs allowed) ----------------
__device__ float  g_dinv[MAXN];
__device__ int    g_deg[MAXN];
__device__ int    g_rowptr[MAXN + 1];
__device__ int    g_cursor[MAXN];
__device__ int    g_bsum[256];
__device__ int    g_boff[256];
__device__ int    g_arrive;
__device__ int    g_flag;
__device__ int    g_csr[MAXE];                  // src index only (4B/edge)
__device__ uint16_t g_h1[(size_t)MAXN * 128];   // fp16 gather buffer (layer 1)
__device__ float    g_buf1[(size_t)MAXN * 128];
__device__ uint16_t g_h2[(size_t)MAXN * 64];    // fp16 gather buffer (layer 2)

// ---------------- packed f32x2 helpers (agg path) ----------------
__device__ __forceinline__ unsigned long long packdup(float x) {
    unsigned long long r;
    asm("mov.b64 %0, {%1, %1};" : "=l"(r) : "f"(x));
    return r;
}
__device__ __forceinline__ unsigned long long pack2(float x, float y) {
    unsigned long long r;
    asm("mov.b64 %0, {%1, %2};" : "=l"(r) : "f"(x), "f"(y));
    return r;
}
__device__ __forceinline__ unsigned long long ffma2v(unsigned long long a,
                                                     unsigned long long b,
                                                     unsigned long long c) {
    unsigned long long d;
    asm("fma.rn.f32x2 %0, %1, %2, %3;" : "=l"(d) : "l"(a), "l"(b), "l"(c));
    return d;
}
__device__ __forceinline__ unsigned long long add2(unsigned long long a,
                                                   unsigned long long b) {
    unsigned long long d;
    asm("add.rn.f32x2 %0, %1, %2;" : "=l"(d) : "l"(a), "l"(b));
    return d;
}
// gather 4 fp16 -> two packed f32x2, fma into acc
__device__ __forceinline__ void fma_h4(unsigned long long& a0, unsigned long long& a1,
                                       uint2 v, unsigned long long nrm) {
    float2 f0 = __half22float2(*(__half2*)&v.x);
    float2 f1 = __half22float2(*(__half2*)&v.y);
    a0 = ffma2v(pack2(f0.x, f0.y), nrm, a0);
    a1 = ffma2v(pack2(f1.x, f1.y), nrm, a1);
}

// ---------------- mma / ldmatrix helpers ----------------
__device__ __forceinline__ uint32_t smem_u32(const void* p) {
    uint32_t a;
    asm("{ .reg .u64 t; cvta.to.shared.u64 t, %1; cvt.u32.u64 %0, t; }"
        : "=r"(a) : "l"(p));
    return a;
}
__device__ __forceinline__ void mma16816(float* d, const uint32_t* a, const uint32_t* b) {
    asm volatile(
        "mma.sync.aligned.m16n8k16.row.col.f32.bf16.bf16.f32 "
        "{%0,%1,%2,%3}, {%4,%5,%6,%7}, {%8,%9}, {%0,%1,%2,%3};"
        : "+f"(d[0]), "+f"(d[1]), "+f"(d[2]), "+f"(d[3])
        : "r"(a[0]), "r"(a[1]), "r"(a[2]), "r"(a[3]), "r"(b[0]), "r"(b[1]));
}
__device__ __forceinline__ void ldsm_x4(uint32_t* r, uint32_t addr) {
    asm volatile("ldmatrix.sync.aligned.m8n8.x4.shared.b16 {%0,%1,%2,%3}, [%4];"
                 : "=r"(r[0]), "=r"(r[1]), "=r"(r[2]), "=r"(r[3]) : "r"(addr));
}
__device__ __forceinline__ void ldsm_x4t(uint32_t* r, uint32_t addr) {
    asm volatile("ldmatrix.sync.aligned.m8n8.x4.trans.shared.b16 {%0,%1,%2,%3}, [%4];"
                 : "=r"(r[0]), "=r"(r[1]), "=r"(r[2]), "=r"(r[3]) : "r"(addr));
}
__device__ __forceinline__ void split_bf16(float x, uint16_t& hi, uint16_t& lo) {
    __nv_bfloat16 h = __float2bfloat16_rn(x);
    __nv_bfloat16 l = __float2bfloat16_rn(x - __bfloat162float(h));
    hi = __bfloat16_as_ushort(h);
    lo = __bfloat16_as_ushort(l);
}

// ---------------- degree / CSR build ----------------
__global__ void k_zero_deg(int n) {
    int i = blockIdx.x * blockDim.x + threadIdx.x;
    if (i < n) g_deg[i] = 0;
    if (i == 0) { g_arrive = 0; g_flag = 0; }
}

__global__ void k_count_deg(const int* __restrict__ ei, int E) {
    int i = blockIdx.x * blockDim.x + threadIdx.x;
    if (i < E) atomicAdd(&g_deg[ei[E + i]], 1);
}

__global__ void __launch_bounds__(256) k_scan_all(int n, int nb) {
    __shared__ int s[256];
    __shared__ int s_go;
    int t = threadIdx.x, b = blockIdx.x;
    int i = b * 256 + t;
    int v = (i < n) ? g_deg[i] : 0;
    if (i < n) g_dinv[i] = rsqrtf((float)v + 1.0f);
    s[t] = v;
    __syncthreads();
#pragma unroll
    for (int off = 1; off < 256; off <<= 1) {
        int a = (t >= off) ? s[t - off] : 0;
        __syncthreads();
        s[t] += a;
        __syncthreads();
    }
    int incl = s[t];
    if (t == 255) {
        g_bsum[b] = incl;
        __threadfence();
        int tk = atomicAdd(&g_arrive, 1);
        s_go = (tk == nb - 1);
    }
    __syncthreads();
    if (s_go) {
        int bv2 = (t < nb) ? g_bsum[t] : 0;
        s[t] = bv2;
        __syncthreads();
#pragma unroll
        for (int off = 1; off < 256; off <<= 1) {
            int a = (t >= off) ? s[t - off] : 0;
            __syncthreads();
            s[t] += a;
            __syncthreads();
        }
        if (t < nb) g_boff[t] = s[t] - bv2;
        __threadfence();
        if (t == 0) atomicExch(&g_flag, 1);
    } else {
        if (t == 0) { while (atomicAdd(&g_flag, 0) == 0) { } }
        __syncthreads();
    }
    int boff = *((volatile int*)&g_boff[b]);
    if (i < n) {
        int r = incl - v + boff;
        g_rowptr[i] = r;
        g_cursor[i] = r;
        if (i == n - 1) g_rowptr[n] = r + v;
    }
}

__global__ void k_scatter(const int* __restrict__ ei, int E) {
    int e = blockIdx.x * blockDim.x + threadIdx.x;
    if (e < E) {
        int s = ei[e];
        int d = ei[E + e];
        int pos = atomicAdd(&g_cursor[d], 1);
        g_csr[pos] = s;                      // src only; norms folded into agg
    }
}

// ---------------- tensor-core GEMM: Hfp16 = X @ W (2 K-phases; 2 blocks/SM) ----------------
// 8 warps in 4x2 grid; warp tile 32 rows x NCOL/2 cols.
// 3xBF16 split (hi*hi + hi*lo + lo*hi), fp32 accumulate via mma.sync m16n8k16.
template <int NCOL, bool RELU>
__global__ void __launch_bounds__(256, 2) k_gemm_mma(
    const float* __restrict__ X, const float* __restrict__ W,
    uint16_t* __restrict__ H16, int nrows)
{
    constexpr int PXP = 72;                         // X phase pitch (64 cols + 8 pad)
    constexpr int PWP = (NCOL == 128) ? 136 : 72;   // W pitch
    constexpr int WC  = NCOL / 2;                   // cols per warp
    constexpr int NPW = WC / 16;                    // b-ldsm pairs per kt

    extern __shared__ uint16_t sm16[];
    uint16_t* sXh = sm16;                  // 128 x PXP
    uint16_t* sXl = sXh + 128 * PXP;
    uint16_t* sWh = sXl + 128 * PXP;       // 64 x PWP
    uint16_t* sWl = sWh + 64 * PWP;

    const int tid  = threadIdx.x;
    const int warp = tid >> 5;
    const int lane = tid & 31;
    const int row0 = blockIdx.x * 128;

    const uint32_t bXh = smem_u32(sXh), bXl = smem_u32(sXl);
    const uint32_t bWh = smem_u32(sWh), bWl = smem_u32(sWl);

    float acc[2][2 * NPW][4];
#pragma unroll
    for (int rs = 0; rs < 2; rs++)
#pragma unroll
        for (int j = 0; j < 2 * NPW; j++) {
            acc[rs][j][0] = 0.f; acc[rs][j][1] = 0.f;
            acc[rs][j][2] = 0.f; acc[rs][j][3] = 0.f;
        }

    const int wr = warp >> 1, wc = warp & 1;
    const int mrow = wr * 32;
    const uint32_t aoff0 = ((uint32_t)(mrow + (lane & 15)) * PXP + ((lane >> 4) << 3)) * 2;
    const uint32_t aoff1 = aoff0 + 16 * PXP * 2;
    const uint32_t boff  = ((uint32_t)(lane & 15) * PWP + ((lane >> 4) << 3) + wc * WC) * 2;

#pragma unroll
    for (int ph = 0; ph < 2; ph++) {
        if (ph) __syncthreads();   // prior phase's reads done before restage

        // stage W[ph*64 .. +64), all NCOL cols: fp32 -> bf16 hi/lo
        for (int i = tid; i < 64 * NCOL / 4; i += 256) {
            float4 w = ((const float4*)(W + ph * 64 * NCOL))[i];
            int k = (4 * i) / NCOL, c = (4 * i) % NCOL;
            uint16_t h0, l0, h1, l1, h2, l2, h3, l3;
            split_bf16(w.x, h0, l0); split_bf16(w.y, h1, l1);
            split_bf16(w.z, h2, l2); split_bf16(w.w, h3, l3);
            *(uint32_t*)(sWh + k * PWP + c)     = (uint32_t)h0 | ((uint32_t)h1 << 16);
            *(uint32_t*)(sWh + k * PWP + c + 2) = (uint32_t)h2 | ((uint32_t)h3 << 16);
            *(uint32_t*)(sWl + k * PWP + c)     = (uint32_t)l0 | ((uint32_t)l1 << 16);
            *(uint32_t*)(sWl + k * PWP + c + 2) = (uint32_t)l2 | ((uint32_t)l3 << 16);
        }

        // stage X[:, ph*64 .. +64): thread = (row tid/2, 32-col half tid&1)
        {
            int r = tid >> 1, half = tid & 1;
            int row = row0 + r;
            uint32_t* dh = (uint32_t*)(sXh + r * PXP + half * 32);
            uint32_t* dl = (uint32_t*)(sXl + r * PXP + half * 32);
            if (row < nrows) {
                const float4* xr = (const float4*)(X + (size_t)row * K_DIM)
                                   + ph * 16 + half * 8;
#pragma unroll 4
                for (int c4 = 0; c4 < 8; c4++) {
                    float4 v = xr[c4];
                    if (RELU) {
                        v.x = fmaxf(v.x, 0.f); v.y = fmaxf(v.y, 0.f);
                        v.z = fmaxf(v.z, 0.f); v.w = fmaxf(v.w, 0.f);
                    }
                    uint16_t h0, l0, h1, l1, h2, l2, h3, l3;
                    split_bf16(v.x, h0, l0); split_bf16(v.y, h1, l1);
                    split_bf16(v.z, h2, l2); split_bf16(v.w, h3, l3);
                    dh[2 * c4]     = (uint32_t)h0 | ((uint32_t)h1 << 16);
                    dh[2 * c4 + 1] = (uint32_t)h2 | ((uint32_t)h3 << 16);
                    dl[2 * c4]     = (uint32_t)l0 | ((uint32_t)l1 << 16);
                    dl[2 * c4 + 1] = (uint32_t)l2 | ((uint32_t)l3 << 16);
                }
            } else {
#pragma unroll 4
                for (int c4 = 0; c4 < 8; c4++) {
                    dh[2 * c4] = 0u; dh[2 * c4 + 1] = 0u;
                    dl[2 * c4] = 0u; dl[2 * c4 + 1] = 0u;
                }
            }
        }
        __syncthreads();

#pragma unroll
        for (int kt = 0; kt < 4; kt++) {
            uint32_t ah0[4], al0[4], ah1[4], al1[4];
            ldsm_x4(ah0, bXh + aoff0 + kt * 32);
            ldsm_x4(al0, bXl + aoff0 + kt * 32);
            ldsm_x4(ah1, bXh + aoff1 + kt * 32);
            ldsm_x4(al1, bXl + aoff1 + kt * 32);
            uint32_t bk = kt * 16 * PWP * 2;
#pragma unroll
            for (int np = 0; np < NPW; np++) {
                uint32_t bh[4], bl[4];
                ldsm_x4t(bh, bWh + boff + bk + np * 32);
                ldsm_x4t(bl, bWl + boff + bk + np * 32);
                mma16816(acc[0][2 * np],     ah0, bh);
                mma16816(acc[0][2 * np + 1], ah0, bh + 2);
                mma16816(acc[0][2 * np],     ah0, bl);
                mma16816(acc[0][2 * np + 1], ah0, bl + 2);
                mma16816(acc[0][2 * np],     al0, bh);
                mma16816(acc[0][2 * np + 1], al0, bh + 2);
                mma16816(acc[1][2 * np],     ah1, bh);
                mma16816(acc[1][2 * np + 1], ah1, bh + 2);
                mma16816(acc[1][2 * np],     ah1, bl);
                mma16816(acc[1][2 * np + 1], ah1, bl + 2);
                mma16816(acc[1][2 * np],     al1, bh);
                mma16816(acc[1][2 * np + 1], al1, bh + 2);
            }
        }
    }

    // epilogue: fp16 H only (bias/dinv/self-loop handled by the agg kernels)
#pragma unroll
    for (int rs = 0; rs < 2; rs++) {
        int r0g = row0 + mrow + rs * 16 + (lane >> 2);
        int r1g = r0g + 8;
#pragma unroll
        for (int j = 0; j < 2 * NPW; j++) {
            int col = wc * WC + j * 8 + (lane & 3) * 2;
            if (r0g < nrows) {
                __half2 hh = __floats2half2_rn(acc[rs][j][0], acc[rs][j][1]);
                *(uint32_t*)(H16 + (size_t)r0g * NCOL + col) = *(uint32_t*)&hh;
            }
            if (r1g < nrows) {
                __half2 hh = __floats2half2_rn(acc[rs][j][2], acc[rs][j][3]);
                *(uint32_t*)(H16 + (size_t)r1g * NCOL + col) = *(uint32_t*)&hh;
            }
        }
    }
}

// ---------- CSR aggregation: OUT[n] = bias + dinv[n]*(dinv[n]*H[n] + sum_e dinv[s]*H[s]) ----------
__global__ void __launch_bounds__(256) k_agg128(
    const uint16_t* __restrict__ H16, const float* __restrict__ bias,
    const float* __restrict__ dinv, float* __restrict__ OUT, int N)
{
    int gw   = (blockIdx.x * 256 + threadIdx.x) >> 5;
    int lane = threadIdx.x & 31;
    if (gw >= N) return;
    int beg = g_rowptr[gw], end = g_rowptr[gw + 1];

    const uint16_t* Hl = H16 + lane * 4;
    unsigned long long a0 = 0ull, a1 = 0ull;
    int j = beg;
    for (; j + 2 <= end; j += 2) {
        int s0i = g_csr[j];          // scalar loads: j has arbitrary parity,
        int s1i = g_csr[j + 1];      // vector int2 would be misaligned
        float n0 = dinv[s0i];
        float n1 = dinv[s1i];
        uint2 v0 = *(const uint2*)(Hl + (size_t)s0i * 128);
        uint2 v1 = *(const uint2*)(Hl + (size_t)s1i * 128);
        fma_h4(a0, a1, v0, packdup(n0));
        fma_h4(a0, a1, v1, packdup(n1));
    }
    if (j < end) {
        int s = g_csr[j];
        uint2 v0 = *(const uint2*)(Hl + (size_t)s * 128);
        fma_h4(a0, a1, v0, packdup(dinv[s]));
    }

    float di = dinv[gw];
    unsigned long long dp = packdup(di);
    uint2 sv = *(const uint2*)(Hl + (size_t)gw * 128);
    float2 s0 = __half22float2(*(__half2*)&sv.x);
    float2 s1 = __half22float2(*(__half2*)&sv.y);
    // a += di * h_self ; out = bias + di * a
    a0 = ffma2v(pack2(s0.x, s0.y), dp, a0);
    a1 = ffma2v(pack2(s1.x, s1.y), dp, a1);
    float2 b0 = *(const float2*)(bias + lane * 4);
    float2 b1 = *(const float2*)(bias + lane * 4 + 2);
    ulonglong2 ob;
    ob.x = ffma2v(a0, dp, pack2(b0.x, b0.y));
    ob.y = ffma2v(a1, dp, pack2(b1.x, b1.y));
    *(ulonglong2*)(OUT + (size_t)gw * 128 + lane * 4) = ob;
}

__global__ void __launch_bounds__(256) k_agg64(
    const uint16_t* __restrict__ H16, const float* __restrict__ bias,
    const float* __restrict__ dinv, float* __restrict__ OUT, int N)
{
    int idx  = blockIdx.x * 256 + threadIdx.x;
    int node = idx >> 4;
    int lane = idx & 15;
    if (node >= N) return;
    int beg = g_rowptr[node], end = g_rowptr[node + 1];

    const uint16_t* Hl = H16 + lane * 4;
    unsigned long long a0 = 0ull, a1 = 0ull;
    int j = beg;
    for (; j + 2 <= end; j += 2) {
        int s0i = g_csr[j];          // scalar loads (parity-safe)
        int s1i = g_csr[j + 1];
        float n0 = dinv[s0i];
        float n1 = dinv[s1i];
        uint2 v0 = *(const uint2*)(Hl + (size_t)s0i * 64);
        uint2 v1 = *(const uint2*)(Hl + (size_t)s1i * 64);
        fma_h4(a0, a1, v0, packdup(n0));
        fma_h4(a0, a1, v1, packdup(n1));
    }
    if (j < end) {
        int s = g_csr[j];
        uint2 v0 = *(const uint2*)(Hl + (size_t)s * 64);
        fma_h4(a0, a1, v0, packdup(dinv[s]));
    }

    float di = dinv[node];
    unsigned long long dp = packdup(di);
    uint2 sv = *(const uint2*)(Hl + (size_t)node * 64);
    float2 s0 = __half22float2(*(__half2*)&sv.x);
    float2 s1 = __half22float2(*(__half2*)&sv.y);
    a0 = ffma2v(pack2(s0.x, s0.y), dp, a0);
    a1 = ffma2v(pack2(s1.x, s1.y), dp, a1);
    float2 b0 = *(const float2*)(bias + lane * 4);
    float2 b1 = *(const float2*)(bias + lane * 4 + 2);
    ulonglong2 ob;
    ob.x = ffma2v(a0, dp, pack2(b0.x, b0.y));
    ob.y = ffma2v(a1, dp, pack2(b1.x, b1.y));
    *(ulonglong2*)(OUT + (size_t)node * 64 + lane * 4) = ob;
}

// ---------------- launch ----------------
extern "C" void kernel_launch(void* const* d_in, const int* in_sizes, int n_in,
                              void* d_out, int out_size)
{
    const float* x  = (const float*)d_in[0];
    const int*   ei = (const int*)d_in[1];
    const float* W1 = (const float*)d_in[2];
    const float* b1 = (const float*)d_in[3];
    const float* W2 = (const float*)d_in[4];
    const float* b2 = (const float*)d_in[5];
    float*       out = (float*)d_out;

    const int N = in_sizes[0] / 128;   // 50000
    const int E = in_sizes[1] / 2;     // 800000

    float* dinv;   cudaGetSymbolAddress((void**)&dinv, g_dinv);
    uint16_t* h1;  cudaGetSymbolAddress((void**)&h1,   g_h1);
    float* buf1;   cudaGetSymbolAddress((void**)&buf1, g_buf1);
    uint16_t* h2;  cudaGetSymbolAddress((void**)&h2,   g_h2);

    const int SM1 = (2 * 128 * 72 + 2 * 64 * 136) * 2;  // 71680
    const int SM2 = (2 * 128 * 72 + 2 * 64 * 72) * 2;   // 55296
    cudaFuncSetAttribute((const void*)k_gemm_mma<128, false>,
                         cudaFuncAttributeMaxDynamicSharedMemorySize, SM1);
    cudaFuncSetAttribute((const void*)k_gemm_mma<64, true>,
                         cudaFuncAttributeMaxDynamicSharedMemorySize, SM2);

    // persistent side stream + fork/join events (host objects only)
    static cudaStream_t s_bld = nullptr;
    static cudaEvent_t  e_fork = nullptr, e_join = nullptr;
    if (s_bld == nullptr) {
        cudaStreamCreateWithFlags(&s_bld, cudaStreamNonBlocking);
        cudaEventCreateWithFlags(&e_fork, cudaEventDisableTiming);
        cudaEventCreateWithFlags(&e_join, cudaEventDisableTiming);
    }

    const int nblkN = (N + 255) / 256;   // 196 (<= 256; co-resident for scan)
    const int nblkE = (E + 255) / 256;
    const int gblocks = (N + 127) / 128; // 391

    // fork: CSR build on side stream, GEMM1 on main stream (independent)
    cudaEventRecord(e_fork, 0);
    cudaStreamWaitEvent(s_bld, e_fork, 0);
    k_zero_deg<<<nblkN, 256, 0, s_bld>>>(N);
    k_count_deg<<<nblkE, 256, 0, s_bld>>>(ei, E);
    k_scan_all<<<nblkN, 256, 0, s_bld>>>(N, nblkN);
    k_scatter<<<nblkE, 256, 0, s_bld>>>(ei, E);
    cudaEventRecord(e_join, s_bld);

    k_gemm_mma<128, false><<<gblocks, 256, SM1>>>(x, W1, h1, N);

    // join: agg needs both h1 (main) and csr/dinv (side)
    cudaStreamWaitEvent(0, e_join, 0);
    k_agg128<<<(N * 32 + 255) / 256, 256>>>(h1, b1, dinv, buf1, N);

    k_gemm_mma<64, true><<<gblocks, 256, SM2>>>(buf1, W2, h2, N);
    k_agg64<<<(N * 16 + 255) / 256, 256>>>(h2, b2, dinv, out, N);
}

// round 17
// speedup vs baseline: 1.1945x; 1.0129x over previous
#include <cuda_runtime.h>
#include <cuda_bf16.h>
#include <cuda_fp16.h>
#include <cstdint>

#define MAXN 50000
#define MAXE 800000
#define K_DIM 128

// ---------------- scratch (__device__ globals; no allocs allowed) ----------------
__device__ float  g_dinv[MAXN];
__device__ int    g_deg[MAXN];
__device__ int    g_rowptr[MAXN + 1];
__device__ int    g_bsum[256];
__device__ int    g_boff[256];
__device__ int    g_arrive;
__device__ int    g_flag;
__device__ int    g_rank[MAXE];                 // edge rank within its dst bucket
__device__ int    g_csr[MAXE];                  // src index only (4B/edge)
__device__ uint16_t g_h1[(size_t)MAXN * 128];   // fp16 gather buffer (layer 1)
__device__ float    g_buf1[(size_t)MAXN * 128];
__device__ uint16_t g_h2[(size_t)MAXN * 64];    // fp16 gather buffer (layer 2)

// ---------------- packed f32x2 helpers (agg path) ----------------
__device__ __forceinline__ unsigned long long packdup(float x) {
    unsigned long long r;
    asm("mov.b64 %0, {%1, %1};" : "=l"(r) : "f"(x));
    return r;
}
__device__ __forceinline__ unsigned long long pack2(float x, float y) {
    unsigned long long r;
    asm("mov.b64 %0, {%1, %2};" : "=l"(r) : "f"(x), "f"(y));
    return r;
}
__device__ __forceinline__ unsigned long long ffma2v(unsigned long long a,
                                                     unsigned long long b,
                                                     unsigned long long c) {
    unsigned long long d;
    asm("fma.rn.f32x2 %0, %1, %2, %3;" : "=l"(d) : "l"(a), "l"(b), "l"(c));
    return d;
}
__device__ __forceinline__ unsigned long long add2(unsigned long long a,
                                                   unsigned long long b) {
    unsigned long long d;
    asm("add.rn.f32x2 %0, %1, %2;" : "=l"(d) : "l"(a), "l"(b));
    return d;
}
// gather 4 fp16 -> two packed f32x2, fma into acc
__device__ __forceinline__ void fma_h4(unsigned long long& a0, unsigned long long& a1,
                                       uint2 v, unsigned long long nrm) {
    float2 f0 = __half22float2(*(__half2*)&v.x);
    float2 f1 = __half22float2(*(__half2*)&v.y);
    a0 = ffma2v(pack2(f0.x, f0.y), nrm, a0);
    a1 = ffma2v(pack2(f1.x, f1.y), nrm, a1);
}

// ---------------- mma / ldmatrix helpers ----------------
__device__ __forceinline__ uint32_t smem_u32(const void* p) {
    uint32_t a;
    asm("{ .reg .u64 t; cvta.to.shared.u64 t, %1; cvt.u32.u64 %0, t; }"
        : "=r"(a) : "l"(p));
    return a;
}
__device__ __forceinline__ void mma16816(float* d, const uint32_t* a, const uint32_t* b) {
    asm volatile(
        "mma.sync.aligned.m16n8k16.row.col.f32.bf16.bf16.f32 "
        "{%0,%1,%2,%3}, {%4,%5,%6,%7}, {%8,%9}, {%0,%1,%2,%3};"
        : "+f"(d[0]), "+f"(d[1]), "+f"(d[2]), "+f"(d[3])
        : "r"(a[0]), "r"(a[1]), "r"(a[2]), "r"(a[3]), "r"(b[0]), "r"(b[1]));
}
__device__ __forceinline__ void ldsm_x4(uint32_t* r, uint32_t addr) {
    asm volatile("ldmatrix.sync.aligned.m8n8.x4.shared.b16 {%0,%1,%2,%3}, [%4];"
                 : "=r"(r[0]), "=r"(r[1]), "=r"(r[2]), "=r"(r[3]) : "r"(addr));
}
__device__ __forceinline__ void ldsm_x4t(uint32_t* r, uint32_t addr) {
    asm volatile("ldmatrix.sync.aligned.m8n8.x4.trans.shared.b16 {%0,%1,%2,%3}, [%4];"
                 : "=r"(r[0]), "=r"(r[1]), "=r"(r[2]), "=r"(r[3]) : "r"(addr));
}
__device__ __forceinline__ void split_bf16(float x, uint16_t& hi, uint16_t& lo) {
    __nv_bfloat16 h = __float2bfloat16_rn(x);
    __nv_bfloat16 l = __float2bfloat16_rn(x - __bfloat162float(h));
    hi = __bfloat16_as_ushort(h);
    lo = __bfloat16_as_ushort(l);
}

// ---------------- degree / CSR build ----------------
__global__ void k_zero_deg(int n) {
    int i = blockIdx.x * blockDim.x + threadIdx.x;
    if (i < n) g_deg[i] = 0;
    if (i == 0) { g_arrive = 0; g_flag = 0; }
}

// count degrees AND record each edge's rank within its dst bucket
__global__ void k_count_rank(const int* __restrict__ ei, int E) {
    int i = blockIdx.x * blockDim.x + threadIdx.x;
    if (i < E) g_rank[i] = atomicAdd(&g_deg[ei[E + i]], 1);
}

__global__ void __launch_bounds__(256) k_scan_all(int n, int nb) {
    __shared__ int s[256];
    __shared__ int s_go;
    int t = threadIdx.x, b = blockIdx.x;
    int i = b * 256 + t;
    int v = (i < n) ? g_deg[i] : 0;
    if (i < n) g_dinv[i] = rsqrtf((float)v + 1.0f);
    s[t] = v;
    __syncthreads();
#pragma unroll
    for (int off = 1; off < 256; off <<= 1) {
        int a = (t >= off) ? s[t - off] : 0;
        __syncthreads();
        s[t] += a;
        __syncthreads();
    }
    int incl = s[t];
    if (t == 255) {
        g_bsum[b] = incl;
        __threadfence();
        int tk = atomicAdd(&g_arrive, 1);
        s_go = (tk == nb - 1);
    }
    __syncthreads();
    if (s_go) {
        int bv2 = (t < nb) ? g_bsum[t] : 0;
        s[t] = bv2;
        __syncthreads();
#pragma unroll
        for (int off = 1; off < 256; off <<= 1) {
            int a = (t >= off) ? s[t - off] : 0;
            __syncthreads();
            s[t] += a;
            __syncthreads();
        }
        if (t < nb) g_boff[t] = s[t] - bv2;
        __threadfence();
        if (t == 0) atomicExch(&g_flag, 1);
    } else {
        if (t == 0) { while (atomicAdd(&g_flag, 0) == 0) { } }
        __syncthreads();
    }
    int boff = *((volatile int*)&g_boff[b]);
    if (i < n) {
        int r = incl - v + boff;
        g_rowptr[i] = r;
        if (i == n - 1) g_rowptr[n] = r + v;
    }
}

// atomic-free scatter: pos = rowptr[dst] + rank[edge]
__global__ void k_scatter(const int* __restrict__ ei, int E) {
    int e = blockIdx.x * blockDim.x + threadIdx.x;
    if (e < E) {
        int s = ei[e];
        int d = ei[E + e];
        g_csr[g_rowptr[d] + g_rank[e]] = s;
    }
}

// ---------------- tensor-core GEMM: Hfp16 = X @ W (2 K-phases; 2 blocks/SM) ----------------
// 8 warps in 4x2 grid; warp tile 32 rows x NCOL/2 cols.
// 3xBF16 split (hi*hi + hi*lo + lo*hi), fp32 accumulate via mma.sync m16n8k16.
template <int NCOL, bool RELU>
__global__ void __launch_bounds__(256, 2) k_gemm_mma(
    const float* __restrict__ X, const float* __restrict__ W,
    uint16_t* __restrict__ H16, int nrows)
{
    constexpr int PXP = 72;                         // X phase pitch (64 cols + 8 pad)
    constexpr int PWP = (NCOL == 128) ? 136 : 72;   // W pitch
    constexpr int WC  = NCOL / 2;                   // cols per warp
    constexpr int NPW = WC / 16;                    // b-ldsm pairs per kt

    extern __shared__ uint16_t sm16[];
    uint16_t* sXh = sm16;                  // 128 x PXP
    uint16_t* sXl = sXh + 128 * PXP;
    uint16_t* sWh = sXl + 128 * PXP;       // 64 x PWP
    uint16_t* sWl = sWh + 64 * PWP;

    const int tid  = threadIdx.x;
    const int warp = tid >> 5;
    const int lane = tid & 31;
    const int row0 = blockIdx.x * 128;

    const uint32_t bXh = smem_u32(sXh), bXl = smem_u32(sXl);
    const uint32_t bWh = smem_u32(sWh), bWl = smem_u32(sWl);

    float acc[2][2 * NPW][4];
#pragma unroll
    for (int rs = 0; rs < 2; rs++)
#pragma unroll
        for (int j = 0; j < 2 * NPW; j++) {
            acc[rs][j][0] = 0.f; acc[rs][j][1] = 0.f;
            acc[rs][j][2] = 0.f; acc[rs][j][3] = 0.f;
        }

    const int wr = warp >> 1, wc = warp & 1;
    const int mrow = wr * 32;
    const uint32_t aoff0 = ((uint32_t)(mrow + (lane & 15)) * PXP + ((lane >> 4) << 3)) * 2;
    const uint32_t aoff1 = aoff0 + 16 * PXP * 2;
    const uint32_t boff  = ((uint32_t)(lane & 15) * PWP + ((lane >> 4) << 3) + wc * WC) * 2;

#pragma unroll
    for (int ph = 0; ph < 2; ph++) {
        if (ph) __syncthreads();   // prior phase's reads done before restage

        // stage W[ph*64 .. +64), all NCOL cols: fp32 -> bf16 hi/lo
        for (int i = tid; i < 64 * NCOL / 4; i += 256) {
            float4 w = ((const float4*)(W + ph * 64 * NCOL))[i];
            int k = (4 * i) / NCOL, c = (4 * i) % NCOL;
            uint16_t h0, l0, h1, l1, h2, l2, h3, l3;
            split_bf16(w.x, h0, l0); split_bf16(w.y, h1, l1);
            split_bf16(w.z, h2, l2); split_bf16(w.w, h3, l3);
            *(uint32_t*)(sWh + k * PWP + c)     = (uint32_t)h0 | ((uint32_t)h1 << 16);
            *(uint32_t*)(sWh + k * PWP + c + 2) = (uint32_t)h2 | ((uint32_t)h3 << 16);
            *(uint32_t*)(sWl + k * PWP + c)     = (uint32_t)l0 | ((uint32_t)l1 << 16);
            *(uint32_t*)(sWl + k * PWP + c + 2) = (uint32_t)l2 | ((uint32_t)l3 << 16);
        }

        // stage X[:, ph*64 .. +64): thread = (row tid/2, 32-col half tid&1)
        {
            int r = tid >> 1, half = tid & 1;
            int row = row0 + r;
            uint32_t* dh = (uint32_t*)(sXh + r * PXP + half * 32);
            uint32_t* dl = (uint32_t*)(sXl + r * PXP + half * 32);
            if (row < nrows) {
                const float4* xr = (const float4*)(X + (size_t)row * K_DIM)
                                   + ph * 16 + half * 8;
#pragma unroll 4
                for (int c4 = 0; c4 < 8; c4++) {
                    float4 v = xr[c4];
                    if (RELU) {
                        v.x = fmaxf(v.x, 0.f); v.y = fmaxf(v.y, 0.f);
                        v.z = fmaxf(v.z, 0.f); v.w = fmaxf(v.w, 0.f);
                    }
                    uint16_t h0, l0, h1, l1, h2, l2, h3, l3;
                    split_bf16(v.x, h0, l0); split_bf16(v.y, h1, l1);
                    split_bf16(v.z, h2, l2); split_bf16(v.w, h3, l3);
                    dh[2 * c4]     = (uint32_t)h0 | ((uint32_t)h1 << 16);
                    dh[2 * c4 + 1] = (uint32_t)h2 | ((uint32_t)h3 << 16);
                    dl[2 * c4]     = (uint32_t)l0 | ((uint32_t)l1 << 16);
                    dl[2 * c4 + 1] = (uint32_t)l2 | ((uint32_t)l3 << 16);
                }
            } else {
#pragma unroll 4
                for (int c4 = 0; c4 < 8; c4++) {
                    dh[2 * c4] = 0u; dh[2 * c4 + 1] = 0u;
                    dl[2 * c4] = 0u; dl[2 * c4 + 1] = 0u;
                }
            }
        }
        __syncthreads();

#pragma unroll
        for (int kt = 0; kt < 4; kt++) {
            uint32_t ah0[4], al0[4], ah1[4], al1[4];
            ldsm_x4(ah0, bXh + aoff0 + kt * 32);
            ldsm_x4(al0, bXl + aoff0 + kt * 32);
            ldsm_x4(ah1, bXh + aoff1 + kt * 32);
            ldsm_x4(al1, bXl + aoff1 + kt * 32);
            uint32_t bk = kt * 16 * PWP * 2;
#pragma unroll
            for (int np = 0; np < NPW; np++) {
                uint32_t bh[4], bl[4];
                ldsm_x4t(bh, bWh + boff + bk + np * 32);
                ldsm_x4t(bl, bWl + boff + bk + np * 32);
                mma16816(acc[0][2 * np],     ah0, bh);
                mma16816(acc[0][2 * np + 1], ah0, bh + 2);
                mma16816(acc[0][2 * np],     ah0, bl);
                mma16816(acc[0][2 * np + 1], ah0, bl + 2);
                mma16816(acc[0][2 * np],     al0, bh);
                mma16816(acc[0][2 * np + 1], al0, bh + 2);
                mma16816(acc[1][2 * np],     ah1, bh);
                mma16816(acc[1][2 * np + 1], ah1, bh + 2);
                mma16816(acc[1][2 * np],     ah1, bl);
                mma16816(acc[1][2 * np + 1], ah1, bl + 2);
                mma16816(acc[1][2 * np],     al1, bh);
                mma16816(acc[1][2 * np + 1], al1, bh + 2);
            }
        }
    }

    // epilogue: fp16 H only (bias/dinv/self-loop handled by the agg kernels)
#pragma unroll
    for (int rs = 0; rs < 2; rs++) {
        int r0g = row0 + mrow + rs * 16 + (lane >> 2);
        int r1g = r0g + 8;
#pragma unroll
        for (int j = 0; j < 2 * NPW; j++) {
            int col = wc * WC + j * 8 + (lane & 3) * 2;
            if (r0g < nrows) {
                __half2 hh = __floats2half2_rn(acc[rs][j][0], acc[rs][j][1]);
                *(uint32_t*)(H16 + (size_t)r0g * NCOL + col) = *(uint32_t*)&hh;
            }
            if (r1g < nrows) {
                __half2 hh = __floats2half2_rn(acc[rs][j][2], acc[rs][j][3]);
                *(uint32_t*)(H16 + (size_t)r1g * NCOL + col) = *(uint32_t*)&hh;
            }
        }
    }
}

// ---------- CSR aggregation: OUT[n] = bias + dinv[n]*(dinv[n]*H[n] + sum_e dinv[s]*H[s]) ----------
__global__ void __launch_bounds__(256) k_agg128(
    const uint16_t* __restrict__ H16, const float* __restrict__ bias,
    const float* __restrict__ dinv, float* __restrict__ OUT, int N)
{
    int gw   = (blockIdx.x * 256 + threadIdx.x) >> 5;
    int lane = threadIdx.x & 31;
    if (gw >= N) return;
    int beg = g_rowptr[gw], end = g_rowptr[gw + 1];

    const uint16_t* Hl = H16 + lane * 4;
    unsigned long long a0 = 0ull, a1 = 0ull;
    int j = beg;
    for (; j + 2 <= end; j += 2) {
        int s0i = g_csr[j];          // scalar loads (parity-safe)
        int s1i = g_csr[j + 1];
        float n0 = dinv[s0i];
        float n1 = dinv[s1i];
        uint2 v0 = *(const uint2*)(Hl + (size_t)s0i * 128);
        uint2 v1 = *(const uint2*)(Hl + (size_t)s1i * 128);
        fma_h4(a0, a1, v0, packdup(n0));
        fma_h4(a0, a1, v1, packdup(n1));
    }
    if (j < end) {
        int s = g_csr[j];
        uint2 v0 = *(const uint2*)(Hl + (size_t)s * 128);
        fma_h4(a0, a1, v0, packdup(dinv[s]));
    }

    float di = dinv[gw];
    unsigned long long dp = packdup(di);
    uint2 sv = *(const uint2*)(Hl + (size_t)gw * 128);
    float2 s0 = __half22float2(*(__half2*)&sv.x);
    float2 s1 = __half22float2(*(__half2*)&sv.y);
    // a += di * h_self ; out = bias + di * a
    a0 = ffma2v(pack2(s0.x, s0.y), dp, a0);
    a1 = ffma2v(pack2(s1.x, s1.y), dp, a1);
    float2 b0 = *(const float2*)(bias + lane * 4);
    float2 b1 = *(const float2*)(bias + lane * 4 + 2);
    ulonglong2 ob;
    ob.x = ffma2v(a0, dp, pack2(b0.x, b0.y));
    ob.y = ffma2v(a1, dp, pack2(b1.x, b1.y));
    *(ulonglong2*)(OUT + (size_t)gw * 128 + lane * 4) = ob;
}

__global__ void __launch_bounds__(256) k_agg64(
    const uint16_t* __restrict__ H16, const float* __restrict__ bias,
    const float* __restrict__ dinv, float* __restrict__ OUT, int N)
{
    int idx  = blockIdx.x * 256 + threadIdx.x;
    int node = idx >> 4;
    int lane = idx & 15;
    if (node >= N) return;
    int beg = g_rowptr[node], end = g_rowptr[node + 1];

    const uint16_t* Hl = H16 + lane * 4;
    unsigned long long a0 = 0ull, a1 = 0ull;
    int j = beg;
    for (; j + 2 <= end; j += 2) {
        int s0i = g_csr[j];          // scalar loads (parity-safe)
        int s1i = g_csr[j + 1];
        float n0 = dinv[s0i];
        float n1 = dinv[s1i];
        uint2 v0 = *(const uint2*)(Hl + (size_t)s0i * 64);
        uint2 v1 = *(const uint2*)(Hl + (size_t)s1i * 64);
        fma_h4(a0, a1, v0, packdup(n0));
        fma_h4(a0, a1, v1, packdup(n1));
    }
    if (j < end) {
        int s = g_csr[j];
        uint2 v0 = *(const uint2*)(Hl + (size_t)s * 64);
        fma_h4(a0, a1, v0, packdup(dinv[s]));
    }

    float di = dinv[node];
    unsigned long long dp = packdup(di);
    uint2 sv = *(const uint2*)(Hl + (size_t)node * 64);
    float2 s0 = __half22float2(*(__half2*)&sv.x);
    float2 s1 = __half22float2(*(__half2*)&sv.y);
    a0 = ffma2v(pack2(s0.x, s0.y), dp, a0);
    a1 = ffma2v(pack2(s1.x, s1.y), dp, a1);
    float2 b0 = *(const float2*)(bias + lane * 4);
    float2 b1 = *(const float2*)(bias + lane * 4 + 2);
    ulonglong2 ob;
    ob.x = ffma2v(a0, dp, pack2(b0.x, b0.y));
    ob.y = ffma2v(a1, dp, pack2(b1.x, b1.y));
    *(ulonglong2*)(OUT + (size_t)node * 64 + lane * 4) = ob;
}

// ---------------- launch ----------------
extern "C" void kernel_launch(void* const* d_in, const int* in_sizes, int n_in,
                              void* d_out, int out_size)
{
    const float* x  = (const float*)d_in[0];
    const int*   ei = (const int*)d_in[1];
    const float* W1 = (const float*)d_in[2];
    const float* b1 = (const float*)d_in[3];
    const float* W2 = (const float*)d_in[4];
    const float* b2 = (const float*)d_in[5];
    float*       out = (float*)d_out;

    const int N = in_sizes[0] / 128;   // 50000
    const int E = in_sizes[1] / 2;     // 800000

    float* dinv;   cudaGetSymbolAddress((void**)&dinv, g_dinv);
    uint16_t* h1;  cudaGetSymbolAddress((void**)&h1,   g_h1);
    float* buf1;   cudaGetSymbolAddress((void**)&buf1, g_buf1);
    uint16_t* h2;  cudaGetSymbolAddress((void**)&h2,   g_h2);

    const int SM1 = (2 * 128 * 72 + 2 * 64 * 136) * 2;  // 71680
    const int SM2 = (2 * 128 * 72 + 2 * 64 * 72) * 2;   // 55296
    cudaFuncSetAttribute((const void*)k_gemm_mma<128, false>,
                         cudaFuncAttributeMaxDynamicSharedMemorySize, SM1);
    cudaFuncSetAttribute((const void*)k_gemm_mma<64, true>,
                         cudaFuncAttributeMaxDynamicSharedMemorySize, SM2);

    // persistent side stream + fork/join events (host objects only)
    static cudaStream_t s_bld = nullptr;
    static cudaEvent_t  e_fork = nullptr, e_join = nullptr;
    if (s_bld == nullptr) {
        cudaStreamCreateWithFlags(&s_bld, cudaStreamNonBlocking);
        cudaEventCreateWithFlags(&e_fork, cudaEventDisableTiming);
        cudaEventCreateWithFlags(&e_join, cudaEventDisableTiming);
    }

    const int nblkN = (N + 255) / 256;   // 196 (<= 256; co-resident for scan)
    const int nblkE = (E + 255) / 256;
    const int gblocks = (N + 127) / 128; // 391

    // fork: CSR build on side stream, GEMM1 on main stream (independent)
    cudaEventRecord(e_fork, 0);
    cudaStreamWaitEvent(s_bld, e_fork, 0);
    k_zero_deg<<<nblkN, 256, 0, s_bld>>>(N);
    k_count_rank<<<nblkE, 256, 0, s_bld>>>(ei, E);
    k_scan_all<<<nblkN, 256, 0, s_bld>>>(N, nblkN);
    k_scatter<<<nblkE, 256, 0, s_bld>>>(ei, E);
    cudaEventRecord(e_join, s_bld);

    k_gemm_mma<128, false><<<gblocks, 256, SM1>>>(x, W1, h1, N);

    // join: agg needs both h1 (main) and csr/dinv (side)
    cudaStreamWaitEvent(0, e_join, 0);
    k_agg128<<<(N * 32 + 255) / 256, 256>>>(h1, b1, dinv, buf1, N);

    k_gemm_mma<64, true><<<gblocks, 256, SM2>>>(buf1, W2, h2, N);
    k_agg64<<<(N * 16 + 255) / 256, 256>>>(h2, b2, dinv, out, N);
}